// round 1
// baseline (speedup 1.0000x reference)
#include <cuda_runtime.h>
#include <cuda_bf16.h>
#include <mma.h>

#define N_NODES 100000
#define D 128
#define N_EDGES 1600000
#define BATCH 500000
#define LN_EPS 1e-5f

using namespace nvcuda;

// Scratch (device globals; no allocation allowed)
__device__ __align__(128) float g_h1[N_NODES * D];   // GEMM out, later LN out
__device__ __align__(128) float g_h2[N_NODES * D];   // aggregation target

#define LDA 136
#define LDB 136
#define LDC 132
#define GEMM_SMEM (4 * 128 * 136 * 2)   // 139264 bytes

// h1 = emb @ W + bias  via bf16 hi/lo split (3 MMAs) for fp32-class accuracy
__global__ void gemm_kernel(const float* __restrict__ emb,
                            const float* __restrict__ W,
                            const float* __restrict__ bias) {
    extern __shared__ __nv_bfloat16 smem[];
    __nv_bfloat16* sAh = smem;
    __nv_bfloat16* sAl = sAh + 128 * LDA;
    __nv_bfloat16* sWh = sAl + 128 * LDA;
    __nv_bfloat16* sWl = sWh + 128 * LDB;
    float* sC = (float*)smem;   // reused after compute (fits in sAh+sAl area)

    int tid = threadIdx.x;
    int wid = tid >> 5;
    int block_row = blockIdx.x * 128;

    for (int i = tid; i < 128 * 128; i += 256) {
        int r = i >> 7, c = i & 127;
        float wv = W[i];
        __nv_bfloat16 whi = __float2bfloat16(wv);
        sWh[r * LDB + c] = whi;
        sWl[r * LDB + c] = __float2bfloat16(wv - __bfloat162float(whi));
        int grow = block_row + r;
        float a = (grow < N_NODES) ? emb[grow * D + c] : 0.f;
        __nv_bfloat16 ahi = __float2bfloat16(a);
        sAh[r * LDA + c] = ahi;
        sAl[r * LDA + c] = __float2bfloat16(a - __bfloat162float(ahi));
    }
    __syncthreads();

    wmma::fragment<wmma::accumulator, 16, 16, 16, float> acc[8];
    #pragma unroll
    for (int c = 0; c < 8; c++) wmma::fill_fragment(acc[c], 0.f);

    #pragma unroll
    for (int k = 0; k < 8; k++) {
        wmma::fragment<wmma::matrix_a, 16, 16, 16, __nv_bfloat16, wmma::row_major> ah, al;
        wmma::load_matrix_sync(ah, sAh + wid * 16 * LDA + k * 16, LDA);
        wmma::load_matrix_sync(al, sAl + wid * 16 * LDA + k * 16, LDA);
        #pragma unroll
        for (int c = 0; c < 8; c++) {
            wmma::fragment<wmma::matrix_b, 16, 16, 16, __nv_bfloat16, wmma::row_major> bh, bl;
            wmma::load_matrix_sync(bh, sWh + k * 16 * LDB + c * 16, LDB);
            wmma::load_matrix_sync(bl, sWl + k * 16 * LDB + c * 16, LDB);
            wmma::mma_sync(acc[c], ah, bh, acc[c]);
            wmma::mma_sync(acc[c], ah, bl, acc[c]);
            wmma::mma_sync(acc[c], al, bh, acc[c]);
        }
    }
    __syncthreads();
    #pragma unroll
    for (int c = 0; c < 8; c++)
        wmma::store_matrix_sync(sC + wid * 16 * LDC + c * 16, acc[c], LDC, wmma::mem_row_major);
    __syncthreads();

    for (int i = tid; i < 128 * 128; i += 256) {
        int r = i >> 7, c = i & 127;
        int grow = block_row + r;
        if (grow < N_NODES)
            g_h1[grow * D + c] = sC[r * LDC + c] + bias[c];
    }
}

__global__ void zero_kernel() {
    int i = blockIdx.x * blockDim.x + threadIdx.x;
    if (i < N_NODES * D / 4) {
        float4 z = make_float4(0.f, 0.f, 0.f, 0.f);
        ((float4*)g_h2)[i] = z;
    }
}

// one warp per edge: gather h1[col] (L2-resident), scale, vector red into h2[row]
__global__ void spmm_kernel(const float* __restrict__ vals,
                            const int* __restrict__ rows,
                            const int* __restrict__ cols) {
    int e = blockIdx.x * 8 + (threadIdx.x >> 5);
    if (e >= N_EDGES) return;
    int lane = threadIdx.x & 31;
    int r = rows[e];
    int c = cols[e];
    float v = vals[e];
    float4 m = ((const float4*)(g_h1 + (size_t)c * D))[lane];
    m.x *= v; m.y *= v; m.z *= v; m.w *= v;
    float* dst = g_h2 + (size_t)r * D + lane * 4;
    asm volatile("red.global.add.v4.f32 [%0], {%1,%2,%3,%4};"
                 :: "l"(dst), "f"(m.x), "f"(m.y), "f"(m.z), "f"(m.w)
                 : "memory");
}

// relu + layernorm, one warp per row; writes into g_h1 (free after spmm)
__global__ void ln_kernel(const float* __restrict__ gamma,
                          const float* __restrict__ beta) {
    int row = blockIdx.x * 4 + (threadIdx.x >> 5);
    if (row >= N_NODES) return;
    int lane = threadIdx.x & 31;
    float4 v = ((const float4*)(g_h2 + (size_t)row * D))[lane];
    v.x = fmaxf(v.x, 0.f); v.y = fmaxf(v.y, 0.f);
    v.z = fmaxf(v.z, 0.f); v.w = fmaxf(v.w, 0.f);

    float s = v.x + v.y + v.z + v.w;
    #pragma unroll
    for (int o = 16; o; o >>= 1) s += __shfl_xor_sync(0xffffffffu, s, o);
    float mu = s * (1.f / 128.f);

    float dx = v.x - mu, dy = v.y - mu, dz = v.z - mu, dw = v.w - mu;
    float q = dx * dx + dy * dy + dz * dz + dw * dw;
    #pragma unroll
    for (int o = 16; o; o >>= 1) q += __shfl_xor_sync(0xffffffffu, q, o);
    float rs = rsqrtf(q * (1.f / 128.f) + LN_EPS);

    float4 g = ((const float4*)gamma)[lane];
    float4 b = ((const float4*)beta)[lane];
    float4 o;
    o.x = dx * rs * g.x + b.x;
    o.y = dy * rs * g.y + b.y;
    o.z = dz * rs * g.z + b.z;
    o.w = dw * rs * g.w + b.w;
    ((float4*)(g_h1 + (size_t)row * D))[lane] = o;
}

// masked batch gather: one warp per output row
__global__ void gather_kernel(const int* __restrict__ x, float* __restrict__ out) {
    int b = blockIdx.x * 8 + (threadIdx.x >> 5);
    if (b >= BATCH) return;
    int lane = threadIdx.x & 31;
    int xv = x[b];
    float4 o = make_float4(0.f, 0.f, 0.f, 0.f);
    if (xv >= 1 && xv <= N_NODES)
        o = ((const float4*)(g_h1 + (size_t)(xv - 1) * D))[lane];
    ((float4*)(out + (size_t)b * D))[lane] = o;
}

extern "C" void kernel_launch(void* const* d_in, const int* in_sizes, int n_in,
                              void* d_out, int out_size) {
    const int*   x     = (const int*)d_in[0];
    const float* emb   = (const float*)d_in[1];
    const float* W     = (const float*)d_in[2];
    const float* bias  = (const float*)d_in[3];
    const float* vals  = (const float*)d_in[4];
    const int*   rows  = (const int*)d_in[5];
    const int*   cols  = (const int*)d_in[6];
    const float* gamma = (const float*)d_in[7];
    const float* beta  = (const float*)d_in[8];
    float* out = (float*)d_out;

    cudaFuncSetAttribute(gemm_kernel, cudaFuncAttributeMaxDynamicSharedMemorySize, GEMM_SMEM);

    gemm_kernel<<<(N_NODES + 127) / 128, 256, GEMM_SMEM>>>(emb, W, bias);
    zero_kernel<<<(N_NODES * D / 4 + 255) / 256, 256>>>();
    spmm_kernel<<<(N_EDGES + 7) / 8, 256>>>(vals, rows, cols);
    ln_kernel<<<(N_NODES + 3) / 4, 128>>>(gamma, beta);
    gather_kernel<<<(BATCH + 7) / 8, 256>>>(x, out);
}

// round 2
// speedup vs baseline: 1.3723x; 1.3723x over previous
#include <cuda_runtime.h>
#include <cuda_bf16.h>
#include <mma.h>

#define N_NODES 100000
#define D 128
#define N_EDGES 1600000
#define BATCH 500000
#define LN_EPS 1e-5f
#define SCAN_CHUNK 1024
#define NBLK ((N_NODES + SCAN_CHUNK - 1) / SCAN_CHUNK)   // 98

using namespace nvcuda;

// Scratch (device globals; no allocation allowed)
__device__ __align__(128) float g_h1[N_NODES * D];   // GEMM output
__device__ __align__(128) float g_h2[N_NODES * D];   // LN output
__device__ __align__(128) int2  g_epack[N_EDGES];    // CSR-permuted {col, val}
__device__ int g_cnt[N_NODES];
__device__ int g_cur[N_NODES];
__device__ int g_rowptr[N_NODES + 1];
__device__ int g_bsum[NBLK];

#define LDA 136
#define LDB 136
#define LDC 132
#define GEMM_SMEM (4 * 128 * 136 * 2)   // 139264 bytes

// ---------------- GEMM: h1 = emb @ W + bias (bf16 hi/lo split, 3 MMAs) ----------------
__global__ void gemm_kernel(const float* __restrict__ emb,
                            const float* __restrict__ W,
                            const float* __restrict__ bias) {
    extern __shared__ __nv_bfloat16 smem[];
    __nv_bfloat16* sAh = smem;
    __nv_bfloat16* sAl = sAh + 128 * LDA;
    __nv_bfloat16* sWh = sAl + 128 * LDA;
    __nv_bfloat16* sWl = sWh + 128 * LDB;
    float* sC = (float*)smem;

    int tid = threadIdx.x;
    int wid = tid >> 5;
    int block_row = blockIdx.x * 128;

    for (int i = tid; i < 128 * 128; i += 256) {
        int r = i >> 7, c = i & 127;
        float wv = W[i];
        __nv_bfloat16 whi = __float2bfloat16(wv);
        sWh[r * LDB + c] = whi;
        sWl[r * LDB + c] = __float2bfloat16(wv - __bfloat162float(whi));
        int grow = block_row + r;
        float a = (grow < N_NODES) ? emb[grow * D + c] : 0.f;
        __nv_bfloat16 ahi = __float2bfloat16(a);
        sAh[r * LDA + c] = ahi;
        sAl[r * LDA + c] = __float2bfloat16(a - __bfloat162float(ahi));
    }
    __syncthreads();

    wmma::fragment<wmma::accumulator, 16, 16, 16, float> acc[8];
    #pragma unroll
    for (int c = 0; c < 8; c++) wmma::fill_fragment(acc[c], 0.f);

    #pragma unroll
    for (int k = 0; k < 8; k++) {
        wmma::fragment<wmma::matrix_a, 16, 16, 16, __nv_bfloat16, wmma::row_major> ah, al;
        wmma::load_matrix_sync(ah, sAh + wid * 16 * LDA + k * 16, LDA);
        wmma::load_matrix_sync(al, sAl + wid * 16 * LDA + k * 16, LDA);
        #pragma unroll
        for (int c = 0; c < 8; c++) {
            wmma::fragment<wmma::matrix_b, 16, 16, 16, __nv_bfloat16, wmma::row_major> bh, bl;
            wmma::load_matrix_sync(bh, sWh + k * 16 * LDB + c * 16, LDB);
            wmma::load_matrix_sync(bl, sWl + k * 16 * LDB + c * 16, LDB);
            wmma::mma_sync(acc[c], ah, bh, acc[c]);
            wmma::mma_sync(acc[c], ah, bl, acc[c]);
            wmma::mma_sync(acc[c], al, bh, acc[c]);
        }
    }
    __syncthreads();
    #pragma unroll
    for (int c = 0; c < 8; c++)
        wmma::store_matrix_sync(sC + wid * 16 * LDC + c * 16, acc[c], LDC, wmma::mem_row_major);
    __syncthreads();

    for (int i = tid; i < 128 * 128; i += 256) {
        int r = i >> 7, c = i & 127;
        int grow = block_row + r;
        if (grow < N_NODES)
            g_h1[grow * D + c] = sC[r * LDC + c] + bias[c];
    }
}

// ---------------- CSR build ----------------
__global__ void zero_cnt_kernel() {
    int i = blockIdx.x * blockDim.x + threadIdx.x;
    if (i < N_NODES) { g_cnt[i] = 0; g_cur[i] = 0; }
}

__global__ void hist_kernel(const int* __restrict__ rows) {
    int e = blockIdx.x * blockDim.x + threadIdx.x;
    if (e < N_EDGES) atomicAdd(&g_cnt[rows[e]], 1);
}

__global__ void scanA_kernel() {
    __shared__ int s[SCAN_CHUNK];
    int tid = threadIdx.x;
    int idx = blockIdx.x * SCAN_CHUNK + tid;
    s[tid] = (idx < N_NODES) ? g_cnt[idx] : 0;
    __syncthreads();
    #pragma unroll
    for (int off = 1; off < SCAN_CHUNK; off <<= 1) {
        int t = (tid >= off) ? s[tid - off] : 0;
        __syncthreads();
        s[tid] += t;
        __syncthreads();
    }
    if (idx < N_NODES) g_rowptr[idx + 1] = s[tid];
    if (tid == SCAN_CHUNK - 1) g_bsum[blockIdx.x] = s[tid];
}

__global__ void scanB_kernel() {
    __shared__ int s[NBLK];
    int tid = threadIdx.x;
    if (tid < NBLK) s[tid] = g_bsum[tid];
    __syncthreads();
    if (tid == 0) {
        int acc = 0;
        #pragma unroll 1
        for (int i = 0; i < NBLK; i++) { int t = s[i]; s[i] = acc; acc += t; }
    }
    __syncthreads();
    if (tid < NBLK) g_bsum[tid] = s[tid];
}

__global__ void scanC_kernel() {
    int idx = blockIdx.x * SCAN_CHUNK + threadIdx.x;
    if (idx < N_NODES) g_rowptr[idx + 1] += g_bsum[blockIdx.x];
    if (idx == 0) g_rowptr[0] = 0;
}

__global__ void scatter_kernel(const float* __restrict__ vals,
                               const int* __restrict__ rows,
                               const int* __restrict__ cols) {
    int e = blockIdx.x * blockDim.x + threadIdx.x;
    if (e >= N_EDGES) return;
    int r = rows[e];
    int p = g_rowptr[r] + atomicAdd(&g_cur[r], 1);
    g_epack[p] = make_int2(cols[e], __float_as_int(vals[e]));
}

// ---------------- fused SpMM + ReLU + LayerNorm: one warp per row ----------------
__global__ void spmm_ln_kernel(const float* __restrict__ gamma,
                               const float* __restrict__ beta) {
    int row = blockIdx.x * 4 + (threadIdx.x >> 5);
    if (row >= N_NODES) return;
    int lane = threadIdx.x & 31;
    int s = g_rowptr[row];
    int e = g_rowptr[row + 1];

    float4 acc = make_float4(0.f, 0.f, 0.f, 0.f);
    for (int i = s; i < e; i++) {
        int2 ev = g_epack[i];                 // broadcast load (all lanes same addr)
        float v = __int_as_float(ev.y);
        float4 m = ((const float4*)(g_h1 + (size_t)ev.x * D))[lane];
        acc.x = fmaf(v, m.x, acc.x);
        acc.y = fmaf(v, m.y, acc.y);
        acc.z = fmaf(v, m.z, acc.z);
        acc.w = fmaf(v, m.w, acc.w);
    }

    // relu
    acc.x = fmaxf(acc.x, 0.f); acc.y = fmaxf(acc.y, 0.f);
    acc.z = fmaxf(acc.z, 0.f); acc.w = fmaxf(acc.w, 0.f);

    // layernorm over 128
    float sm = acc.x + acc.y + acc.z + acc.w;
    #pragma unroll
    for (int o = 16; o; o >>= 1) sm += __shfl_xor_sync(0xffffffffu, sm, o);
    float mu = sm * (1.f / 128.f);

    float dx = acc.x - mu, dy = acc.y - mu, dz = acc.z - mu, dw = acc.w - mu;
    float q = dx * dx + dy * dy + dz * dz + dw * dw;
    #pragma unroll
    for (int o = 16; o; o >>= 1) q += __shfl_xor_sync(0xffffffffu, q, o);
    float rs = rsqrtf(q * (1.f / 128.f) + LN_EPS);

    float4 g = ((const float4*)gamma)[lane];
    float4 b = ((const float4*)beta)[lane];
    float4 o;
    o.x = dx * rs * g.x + b.x;
    o.y = dy * rs * g.y + b.y;
    o.z = dz * rs * g.z + b.z;
    o.w = dw * rs * g.w + b.w;
    ((float4*)(g_h2 + (size_t)row * D))[lane] = o;
}

// ---------------- masked batch gather ----------------
__global__ void gather_kernel(const int* __restrict__ x, float* __restrict__ out) {
    int b = blockIdx.x * 8 + (threadIdx.x >> 5);
    if (b >= BATCH) return;
    int lane = threadIdx.x & 31;
    int xv = x[b];
    float4 o = make_float4(0.f, 0.f, 0.f, 0.f);
    if (xv >= 1 && xv <= N_NODES)
        o = ((const float4*)(g_h2 + (size_t)(xv - 1) * D))[lane];
    ((float4*)(out + (size_t)b * D))[lane] = o;
}

extern "C" void kernel_launch(void* const* d_in, const int* in_sizes, int n_in,
                              void* d_out, int out_size) {
    const int*   x     = (const int*)d_in[0];
    const float* emb   = (const float*)d_in[1];
    const float* W     = (const float*)d_in[2];
    const float* bias  = (const float*)d_in[3];
    const float* vals  = (const float*)d_in[4];
    const int*   rows  = (const int*)d_in[5];
    const int*   cols  = (const int*)d_in[6];
    const float* gamma = (const float*)d_in[7];
    const float* beta  = (const float*)d_in[8];
    float* out = (float*)d_out;

    cudaFuncSetAttribute(gemm_kernel, cudaFuncAttributeMaxDynamicSharedMemorySize, GEMM_SMEM);

    gemm_kernel<<<(N_NODES + 127) / 128, 256, GEMM_SMEM>>>(emb, W, bias);
    zero_cnt_kernel<<<(N_NODES + 255) / 256, 256>>>();
    hist_kernel<<<(N_EDGES + 255) / 256, 256>>>(rows);
    scanA_kernel<<<NBLK, SCAN_CHUNK>>>();
    scanB_kernel<<<1, 128>>>();
    scanC_kernel<<<NBLK, SCAN_CHUNK>>>();
    scatter_kernel<<<(N_EDGES + 255) / 256, 256>>>(vals, rows, cols);
    spmm_ln_kernel<<<(N_NODES + 3) / 4, 128>>>(gamma, beta);
    gather_kernel<<<(BATCH + 7) / 8, 256>>>(x, out);
}

// round 4
// speedup vs baseline: 1.4244x; 1.0380x over previous
#include <cuda_runtime.h>
#include <cuda_bf16.h>
#include <mma.h>

#define N_NODES 100000
#define D 128
#define N_EDGES 1600000
#define BATCH 500000
#define LN_EPS 1e-5f
#define SCAN_CHUNK 1024
#define NBLK ((N_NODES + SCAN_CHUNK - 1) / SCAN_CHUNK)   // 98

using namespace nvcuda;

// Scratch (device globals; no allocation allowed)
__device__ __align__(128) float g_h1[N_NODES * D];   // GEMM output
__device__ __align__(128) float g_h2[N_NODES * D];   // LN output
__device__ __align__(128) int2  g_epack[N_EDGES];    // CSR-permuted {col, val}
__device__ int g_cnt[N_NODES];
__device__ int g_cur[N_NODES];
__device__ int g_rowptr[N_NODES + 1];
__device__ int g_bsum[NBLK];

#define LDA 136
#define LDB 136
#define LDC 132
#define BLK_ROWS 64
// smem: W hi/lo (128*136*2*2B = 69632) + A hi/lo (64*136*2*2B = 34816) = 104448
#define GEMM_SMEM (128 * LDB * 2 * 2 + BLK_ROWS * LDA * 2 * 2)

// ---------------- GEMM: h1 = emb @ W + bias (bf16 hi/lo split, 3 MMAs) ----------------
// 64-row tiles, 2 CTAs/SM. 8 warps in 4x2 grid: warp = 16 rows x 64 cols.
__global__ void gemm_kernel(const float* __restrict__ emb,
                            const float* __restrict__ W,
                            const float* __restrict__ bias) {
    extern __shared__ __nv_bfloat16 smem[];
    __nv_bfloat16* sWh = smem;
    __nv_bfloat16* sWl = sWh + 128 * LDB;
    __nv_bfloat16* sAh = sWl + 128 * LDB;
    __nv_bfloat16* sAl = sAh + BLK_ROWS * LDA;
    float* sC = (float*)sAh;    // reuse A area for C staging (64*132*4 = 33792 <= 34816)

    int tid = threadIdx.x;
    int wid = tid >> 5;
    int wr = wid >> 1;          // 0..3  (16-row group)
    int wc = wid & 1;           // 0..1  (64-col group)
    int block_row = blockIdx.x * BLK_ROWS;

    for (int i = tid; i < 128 * 128; i += 256) {
        int r = i >> 7, c = i & 127;
        float wv = W[i];
        __nv_bfloat16 whi = __float2bfloat16(wv);
        sWh[r * LDB + c] = whi;
        sWl[r * LDB + c] = __float2bfloat16(wv - __bfloat162float(whi));
    }
    for (int i = tid; i < BLK_ROWS * 128; i += 256) {
        int r = i >> 7, c = i & 127;
        int grow = block_row + r;
        float a = (grow < N_NODES) ? emb[(size_t)grow * D + c] : 0.f;
        __nv_bfloat16 ahi = __float2bfloat16(a);
        sAh[r * LDA + c] = ahi;
        sAl[r * LDA + c] = __float2bfloat16(a - __bfloat162float(ahi));
    }
    __syncthreads();

    wmma::fragment<wmma::accumulator, 16, 16, 16, float> acc[4];
    #pragma unroll
    for (int c = 0; c < 4; c++) wmma::fill_fragment(acc[c], 0.f);

    #pragma unroll
    for (int k = 0; k < 8; k++) {
        wmma::fragment<wmma::matrix_a, 16, 16, 16, __nv_bfloat16, wmma::row_major> ah, al;
        wmma::load_matrix_sync(ah, sAh + wr * 16 * LDA + k * 16, LDA);
        wmma::load_matrix_sync(al, sAl + wr * 16 * LDA + k * 16, LDA);
        #pragma unroll
        for (int c = 0; c < 4; c++) {
            int cc = wc * 64 + c * 16;
            wmma::fragment<wmma::matrix_b, 16, 16, 16, __nv_bfloat16, wmma::row_major> bh, bl;
            wmma::load_matrix_sync(bh, sWh + k * 16 * LDB + cc, LDB);
            wmma::load_matrix_sync(bl, sWl + k * 16 * LDB + cc, LDB);
            wmma::mma_sync(acc[c], ah, bh, acc[c]);
            wmma::mma_sync(acc[c], ah, bl, acc[c]);
            wmma::mma_sync(acc[c], al, bh, acc[c]);
        }
    }
    __syncthreads();
    #pragma unroll
    for (int c = 0; c < 4; c++)
        wmma::store_matrix_sync(sC + wr * 16 * LDC + wc * 64 + c * 16, acc[c],
                                LDC, wmma::mem_row_major);
    __syncthreads();

    for (int i = tid; i < BLK_ROWS * 128; i += 256) {
        int r = i >> 7, c = i & 127;
        int grow = block_row + r;
        if (grow < N_NODES)
            g_h1[(size_t)grow * D + c] = sC[r * LDC + c] + bias[c];
    }
}

// ---------------- CSR build ----------------
__global__ void zero_cnt_kernel() {
    int i = blockIdx.x * blockDim.x + threadIdx.x;
    if (i < N_NODES) { g_cnt[i] = 0; g_cur[i] = 0; }
}

__global__ void hist_kernel(const int* __restrict__ rows) {
    int e = blockIdx.x * blockDim.x + threadIdx.x;
    if (e < N_EDGES) atomicAdd(&g_cnt[rows[e]], 1);
}

__global__ void scanA_kernel() {
    __shared__ int s[SCAN_CHUNK];
    int tid = threadIdx.x;
    int idx = blockIdx.x * SCAN_CHUNK + tid;
    s[tid] = (idx < N_NODES) ? g_cnt[idx] : 0;
    __syncthreads();
    #pragma unroll
    for (int off = 1; off < SCAN_CHUNK; off <<= 1) {
        int t = (tid >= off) ? s[tid - off] : 0;
        __syncthreads();
        s[tid] += t;
        __syncthreads();
    }
    if (idx < N_NODES) g_rowptr[idx + 1] = s[tid];
    if (tid == SCAN_CHUNK - 1) g_bsum[blockIdx.x] = s[tid];
}

__global__ void scanB_kernel() {
    __shared__ int s[NBLK];
    int tid = threadIdx.x;
    if (tid < NBLK) s[tid] = g_bsum[tid];
    __syncthreads();
    if (tid == 0) {
        int acc = 0;
        #pragma unroll 1
        for (int i = 0; i < NBLK; i++) { int t = s[i]; s[i] = acc; acc += t; }
    }
    __syncthreads();
    if (tid < NBLK) g_bsum[tid] = s[tid];
}

__global__ void scanC_kernel() {
    int idx = blockIdx.x * SCAN_CHUNK + threadIdx.x;
    if (idx < N_NODES) g_rowptr[idx + 1] += g_bsum[blockIdx.x];
    if (idx == 0) g_rowptr[0] = 0;
}

__global__ void scatter_kernel(const float* __restrict__ vals,
                               const int* __restrict__ rows,
                               const int* __restrict__ cols) {
    int e = blockIdx.x * blockDim.x + threadIdx.x;
    if (e >= N_EDGES) return;
    int r = rows[e];
    int p = g_rowptr[r] + atomicAdd(&g_cur[r], 1);
    g_epack[p] = make_int2(cols[e], __float_as_int(vals[e]));
}

// ---------------- fused SpMM + ReLU + LayerNorm: one warp per row ----------------
// Edge list staged with ONE coalesced load per 32 edges, broadcast via shfl;
// all feature gathers are independent -> L2-bandwidth bound.
__global__ void spmm_ln_kernel(const float* __restrict__ gamma,
                               const float* __restrict__ beta) {
    int row = blockIdx.x * 4 + (threadIdx.x >> 5);
    if (row >= N_NODES) return;
    int lane = threadIdx.x & 31;
    int s = g_rowptr[row];
    int e = g_rowptr[row + 1];

    float4 acc = make_float4(0.f, 0.f, 0.f, 0.f);
    for (int base = s; base < e; base += 32) {
        int n = min(32, e - base);
        int2 ev = make_int2(0, 0);
        if (base + lane < e) ev = g_epack[base + lane];
        for (int j = 0; j < n; j++) {
            int   c = __shfl_sync(0xffffffffu, ev.x, j);
            float v = __int_as_float(__shfl_sync(0xffffffffu, ev.y, j));
            float4 m = ((const float4*)(g_h1 + (size_t)c * D))[lane];
            acc.x = fmaf(v, m.x, acc.x);
            acc.y = fmaf(v, m.y, acc.y);
            acc.z = fmaf(v, m.z, acc.z);
            acc.w = fmaf(v, m.w, acc.w);
        }
    }

    // relu
    acc.x = fmaxf(acc.x, 0.f); acc.y = fmaxf(acc.y, 0.f);
    acc.z = fmaxf(acc.z, 0.f); acc.w = fmaxf(acc.w, 0.f);

    // layernorm over 128
    float sm = acc.x + acc.y + acc.z + acc.w;
    #pragma unroll
    for (int o = 16; o; o >>= 1) sm += __shfl_xor_sync(0xffffffffu, sm, o);
    float mu = sm * (1.f / 128.f);

    float dx = acc.x - mu, dy = acc.y - mu, dz = acc.z - mu, dw = acc.w - mu;
    float q = dx * dx + dy * dy + dz * dz + dw * dw;
    #pragma unroll
    for (int o = 16; o; o >>= 1) q += __shfl_xor_sync(0xffffffffu, q, o);
    float rs = rsqrtf(q * (1.f / 128.f) + LN_EPS);

    float4 g = ((const float4*)gamma)[lane];
    float4 b = ((const float4*)beta)[lane];
    float4 o;
    o.x = dx * rs * g.x + b.x;
    o.y = dy * rs * g.y + b.y;
    o.z = dz * rs * g.z + b.z;
    o.w = dw * rs * g.w + b.w;
    ((float4*)(g_h2 + (size_t)row * D))[lane] = o;
}

// ---------------- masked batch gather ----------------
__global__ void gather_kernel(const int* __restrict__ x, float* __restrict__ out) {
    int b = blockIdx.x * 8 + (threadIdx.x >> 5);
    if (b >= BATCH) return;
    int lane = threadIdx.x & 31;
    int xv = x[b];
    float4 o = make_float4(0.f, 0.f, 0.f, 0.f);
    if (xv >= 1 && xv <= N_NODES)
        o = ((const float4*)(g_h2 + (size_t)(xv - 1) * D))[lane];
    ((float4*)(out + (size_t)b * D))[lane] = o;
}

extern "C" void kernel_launch(void* const* d_in, const int* in_sizes, int n_in,
                              void* d_out, int out_size) {
    const int*   x     = (const int*)d_in[0];
    const float* emb   = (const float*)d_in[1];
    const float* W     = (const float*)d_in[2];
    const float* bias  = (const float*)d_in[3];
    const float* vals  = (const float*)d_in[4];
    const int*   rows  = (const int*)d_in[5];
    const int*   cols  = (const int*)d_in[6];
    const float* gamma = (const float*)d_in[7];
    const float* beta  = (const float*)d_in[8];
    float* out = (float*)d_out;

    cudaFuncSetAttribute(gemm_kernel, cudaFuncAttributeMaxDynamicSharedMemorySize, GEMM_SMEM);

    gemm_kernel<<<(N_NODES + BLK_ROWS - 1) / BLK_ROWS, 256, GEMM_SMEM>>>(emb, W, bias);
    zero_cnt_kernel<<<(N_NODES + 255) / 256, 256>>>();
    hist_kernel<<<(N_EDGES + 255) / 256, 256>>>(rows);
    scanA_kernel<<<NBLK, SCAN_CHUNK>>>();
    scanB_kernel<<<1, 128>>>();
    scanC_kernel<<<NBLK, SCAN_CHUNK>>>();
    scatter_kernel<<<(N_EDGES + 255) / 256, 256>>>(vals, rows, cols);
    spmm_ln_kernel<<<(N_NODES + 3) / 4, 128>>>(gamma, beta);
    gather_kernel<<<(BATCH + 7) / 8, 256>>>(x, out);
}

// round 5
// speedup vs baseline: 1.5591x; 1.0946x over previous
#include <cuda_runtime.h>
#include <cuda_bf16.h>
#include <mma.h>

#define N_NODES 100000
#define D 128
#define N_EDGES 1600000
#define BATCH 500000
#define LN_EPS 1e-5f
#define SCAN_CHUNK 1024
#define NBLK ((N_NODES + SCAN_CHUNK - 1) / SCAN_CHUNK)   // 98

using namespace nvcuda;

// Scratch (device globals; no allocation allowed)
__device__ __align__(128) float g_h1[N_NODES * D];   // GEMM output
__device__ __align__(128) float g_h2[N_NODES * D];   // LN output
__device__ __align__(128) int2  g_epack[N_EDGES];    // CSR-permuted {col, val}
__device__ int g_eloc[N_EDGES];                      // intra-row slot per edge
__device__ int g_cnt[N_NODES];
__device__ int g_rowptr[N_NODES + 1];
__device__ int g_bsum[NBLK];

#define LDA 136
#define LDB 136
#define LDC 132
#define BLK_ROWS 64
#define GEMM_SMEM (128 * LDB * 2 * 2 + BLK_ROWS * LDA * 2 * 2)   // 104448

// ---------------- GEMM: h1 = emb @ W + bias (bf16 hi/lo split, 3 MMAs) ----------------
__global__ void gemm_kernel(const float* __restrict__ emb,
                            const float* __restrict__ W,
                            const float* __restrict__ bias) {
    extern __shared__ __nv_bfloat16 smem[];
    __nv_bfloat16* sWh = smem;
    __nv_bfloat16* sWl = sWh + 128 * LDB;
    __nv_bfloat16* sAh = sWl + 128 * LDB;
    __nv_bfloat16* sAl = sAh + BLK_ROWS * LDA;
    float* sC = (float*)sAh;    // reuse A area (64*132*4 = 33792 <= 34816)

    int tid = threadIdx.x;
    int wid = tid >> 5;
    int wr = wid >> 1;
    int wc = wid & 1;
    int block_row = blockIdx.x * BLK_ROWS;

    for (int i = tid; i < 128 * 128; i += 256) {
        int r = i >> 7, c = i & 127;
        float wv = W[i];
        __nv_bfloat16 whi = __float2bfloat16(wv);
        sWh[r * LDB + c] = whi;
        sWl[r * LDB + c] = __float2bfloat16(wv - __bfloat162float(whi));
    }
    for (int i = tid; i < BLK_ROWS * 128; i += 256) {
        int r = i >> 7, c = i & 127;
        int grow = block_row + r;
        float a = (grow < N_NODES) ? emb[(size_t)grow * D + c] : 0.f;
        __nv_bfloat16 ahi = __float2bfloat16(a);
        sAh[r * LDA + c] = ahi;
        sAl[r * LDA + c] = __float2bfloat16(a - __bfloat162float(ahi));
    }
    __syncthreads();

    wmma::fragment<wmma::accumulator, 16, 16, 16, float> acc[4];
    #pragma unroll
    for (int c = 0; c < 4; c++) wmma::fill_fragment(acc[c], 0.f);

    #pragma unroll
    for (int k = 0; k < 8; k++) {
        wmma::fragment<wmma::matrix_a, 16, 16, 16, __nv_bfloat16, wmma::row_major> ah, al;
        wmma::load_matrix_sync(ah, sAh + wr * 16 * LDA + k * 16, LDA);
        wmma::load_matrix_sync(al, sAl + wr * 16 * LDA + k * 16, LDA);
        #pragma unroll
        for (int c = 0; c < 4; c++) {
            int cc = wc * 64 + c * 16;
            wmma::fragment<wmma::matrix_b, 16, 16, 16, __nv_bfloat16, wmma::row_major> bh, bl;
            wmma::load_matrix_sync(bh, sWh + k * 16 * LDB + cc, LDB);
            wmma::load_matrix_sync(bl, sWl + k * 16 * LDB + cc, LDB);
            wmma::mma_sync(acc[c], ah, bh, acc[c]);
            wmma::mma_sync(acc[c], ah, bl, acc[c]);
            wmma::mma_sync(acc[c], al, bh, acc[c]);
        }
    }
    __syncthreads();
    #pragma unroll
    for (int c = 0; c < 4; c++)
        wmma::store_matrix_sync(sC + wr * 16 * LDC + wc * 64 + c * 16, acc[c],
                                LDC, wmma::mem_row_major);
    __syncthreads();

    for (int i = tid; i < BLK_ROWS * 128; i += 256) {
        int r = i >> 7, c = i & 127;
        int grow = block_row + r;
        if (grow < N_NODES)
            g_h1[(size_t)grow * D + c] = sC[r * LDC + c] + bias[c];
    }
}

// ---------------- CSR build ----------------
__global__ void zero_cnt_kernel() {
    int i = blockIdx.x * blockDim.x + threadIdx.x;
    if (i < N_NODES) g_cnt[i] = 0;
}

// histogram + record intra-row slot (single atomic pass over edges)
__global__ void hist_kernel(const int* __restrict__ rows) {
    int e = blockIdx.x * blockDim.x + threadIdx.x;
    if (e < N_EDGES) g_eloc[e] = atomicAdd(&g_cnt[rows[e]], 1);
}

__global__ void scanA_kernel() {
    __shared__ int s[SCAN_CHUNK];
    int tid = threadIdx.x;
    int idx = blockIdx.x * SCAN_CHUNK + tid;
    s[tid] = (idx < N_NODES) ? g_cnt[idx] : 0;
    __syncthreads();
    #pragma unroll
    for (int off = 1; off < SCAN_CHUNK; off <<= 1) {
        int t = (tid >= off) ? s[tid - off] : 0;
        __syncthreads();
        s[tid] += t;
        __syncthreads();
    }
    if (idx < N_NODES) g_rowptr[idx + 1] = s[tid];
    if (tid == SCAN_CHUNK - 1) g_bsum[blockIdx.x] = s[tid];
}

__global__ void scanB_kernel() {
    __shared__ int s[NBLK];
    int tid = threadIdx.x;
    if (tid < NBLK) s[tid] = g_bsum[tid];
    __syncthreads();
    if (tid == 0) {
        int acc = 0;
        #pragma unroll 1
        for (int i = 0; i < NBLK; i++) { int t = s[i]; s[i] = acc; acc += t; }
    }
    __syncthreads();
    if (tid < NBLK) g_bsum[tid] = s[tid];
}

__global__ void scanC_kernel() {
    int idx = blockIdx.x * SCAN_CHUNK + threadIdx.x;
    if (idx < N_NODES) g_rowptr[idx + 1] += g_bsum[blockIdx.x];
    if (idx == 0) g_rowptr[0] = 0;
}

// pure computed store — no atomics
__global__ void scatter_kernel(const float* __restrict__ vals,
                               const int* __restrict__ rows,
                               const int* __restrict__ cols) {
    int e = blockIdx.x * blockDim.x + threadIdx.x;
    if (e >= N_EDGES) return;
    int p = g_rowptr[rows[e]] + g_eloc[e];
    g_epack[p] = make_int2(cols[e], __float_as_int(vals[e]));
}

// ---------------- fused SpMM + ReLU + LayerNorm: one warp per row ----------------
// Coalesced edge staging + shfl broadcast; inner loop unrolled x4 so four
// independent float4 gathers are in flight (MLP=4) before any FMA consumes.
__global__ void spmm_ln_kernel(const float* __restrict__ gamma,
                               const float* __restrict__ beta) {
    int row = blockIdx.x * 4 + (threadIdx.x >> 5);
    if (row >= N_NODES) return;
    int lane = threadIdx.x & 31;
    int s = g_rowptr[row];
    int e = g_rowptr[row + 1];

    float4 acc = make_float4(0.f, 0.f, 0.f, 0.f);
    for (int base = s; base < e; base += 32) {
        int n = min(32, e - base);
        int2 ev = make_int2(0, 0);
        if (base + lane < e) ev = g_epack[base + lane];
        int j = 0;
        for (; j + 4 <= n; j += 4) {
            int c0 = __shfl_sync(0xffffffffu, ev.x, j);
            int c1 = __shfl_sync(0xffffffffu, ev.x, j + 1);
            int c2 = __shfl_sync(0xffffffffu, ev.x, j + 2);
            int c3 = __shfl_sync(0xffffffffu, ev.x, j + 3);
            float v0 = __int_as_float(__shfl_sync(0xffffffffu, ev.y, j));
            float v1 = __int_as_float(__shfl_sync(0xffffffffu, ev.y, j + 1));
            float v2 = __int_as_float(__shfl_sync(0xffffffffu, ev.y, j + 2));
            float v3 = __int_as_float(__shfl_sync(0xffffffffu, ev.y, j + 3));
            float4 m0 = ((const float4*)(g_h1 + (size_t)c0 * D))[lane];
            float4 m1 = ((const float4*)(g_h1 + (size_t)c1 * D))[lane];
            float4 m2 = ((const float4*)(g_h1 + (size_t)c2 * D))[lane];
            float4 m3 = ((const float4*)(g_h1 + (size_t)c3 * D))[lane];
            acc.x = fmaf(v0, m0.x, acc.x); acc.y = fmaf(v0, m0.y, acc.y);
            acc.z = fmaf(v0, m0.z, acc.z); acc.w = fmaf(v0, m0.w, acc.w);
            acc.x = fmaf(v1, m1.x, acc.x); acc.y = fmaf(v1, m1.y, acc.y);
            acc.z = fmaf(v1, m1.z, acc.z); acc.w = fmaf(v1, m1.w, acc.w);
            acc.x = fmaf(v2, m2.x, acc.x); acc.y = fmaf(v2, m2.y, acc.y);
            acc.z = fmaf(v2, m2.z, acc.z); acc.w = fmaf(v2, m2.w, acc.w);
            acc.x = fmaf(v3, m3.x, acc.x); acc.y = fmaf(v3, m3.y, acc.y);
            acc.z = fmaf(v3, m3.z, acc.z); acc.w = fmaf(v3, m3.w, acc.w);
        }
        for (; j < n; j++) {
            int   c = __shfl_sync(0xffffffffu, ev.x, j);
            float v = __int_as_float(__shfl_sync(0xffffffffu, ev.y, j));
            float4 m = ((const float4*)(g_h1 + (size_t)c * D))[lane];
            acc.x = fmaf(v, m.x, acc.x); acc.y = fmaf(v, m.y, acc.y);
            acc.z = fmaf(v, m.z, acc.z); acc.w = fmaf(v, m.w, acc.w);
        }
    }

    acc.x = fmaxf(acc.x, 0.f); acc.y = fmaxf(acc.y, 0.f);
    acc.z = fmaxf(acc.z, 0.f); acc.w = fmaxf(acc.w, 0.f);

    float sm = acc.x + acc.y + acc.z + acc.w;
    #pragma unroll
    for (int o = 16; o; o >>= 1) sm += __shfl_xor_sync(0xffffffffu, sm, o);
    float mu = sm * (1.f / 128.f);

    float dx = acc.x - mu, dy = acc.y - mu, dz = acc.z - mu, dw = acc.w - mu;
    float q = dx * dx + dy * dy + dz * dz + dw * dw;
    #pragma unroll
    for (int o = 16; o; o >>= 1) q += __shfl_xor_sync(0xffffffffu, q, o);
    float rs = rsqrtf(q * (1.f / 128.f) + LN_EPS);

    float4 g = ((const float4*)gamma)[lane];
    float4 b = ((const float4*)beta)[lane];
    float4 o;
    o.x = dx * rs * g.x + b.x;
    o.y = dy * rs * g.y + b.y;
    o.z = dz * rs * g.z + b.z;
    o.w = dw * rs * g.w + b.w;
    ((float4*)(g_h2 + (size_t)row * D))[lane] = o;
}

// ---------------- masked batch gather: 2 rows per warp (MLP=2 on reads) ----------------
__global__ void gather_kernel(const int* __restrict__ x, float* __restrict__ out) {
    int b0 = (blockIdx.x * 8 + (threadIdx.x >> 5)) * 2;
    if (b0 >= BATCH) return;
    int lane = threadIdx.x & 31;

    int x0 = x[b0];
    int x1 = (b0 + 1 < BATCH) ? x[b0 + 1] : 0;
    float4 o0 = make_float4(0.f, 0.f, 0.f, 0.f);
    float4 o1 = o0;
    if (x0 >= 1 && x0 <= N_NODES)
        o0 = ((const float4*)(g_h2 + (size_t)(x0 - 1) * D))[lane];
    if (x1 >= 1 && x1 <= N_NODES)
        o1 = ((const float4*)(g_h2 + (size_t)(x1 - 1) * D))[lane];
    ((float4*)(out + (size_t)b0 * D))[lane] = o0;
    if (b0 + 1 < BATCH)
        ((float4*)(out + (size_t)(b0 + 1) * D))[lane] = o1;
}

extern "C" void kernel_launch(void* const* d_in, const int* in_sizes, int n_in,
                              void* d_out, int out_size) {
    const int*   x     = (const int*)d_in[0];
    const float* emb   = (const float*)d_in[1];
    const float* W     = (const float*)d_in[2];
    const float* bias  = (const float*)d_in[3];
    const float* vals  = (const float*)d_in[4];
    const int*   rows  = (const int*)d_in[5];
    const int*   cols  = (const int*)d_in[6];
    const float* gamma = (const float*)d_in[7];
    const float* beta  = (const float*)d_in[8];
    float* out = (float*)d_out;

    cudaFuncSetAttribute(gemm_kernel, cudaFuncAttributeMaxDynamicSharedMemorySize, GEMM_SMEM);

    gemm_kernel<<<(N_NODES + BLK_ROWS - 1) / BLK_ROWS, 256, GEMM_SMEM>>>(emb, W, bias);
    zero_cnt_kernel<<<(N_NODES + 255) / 256, 256>>>();
    hist_kernel<<<(N_EDGES + 255) / 256, 256>>>(rows);
    scanA_kernel<<<NBLK, SCAN_CHUNK>>>();
    scanB_kernel<<<1, 128>>>();
    scanC_kernel<<<NBLK, SCAN_CHUNK>>>();
    scatter_kernel<<<(N_EDGES + 255) / 256, 256>>>(vals, rows, cols);
    spmm_ln_kernel<<<(N_NODES + 3) / 4, 128>>>(gamma, beta);
    gather_kernel<<<(BATCH + 15) / 16, 256>>>(x, out);
}

// round 6
// speedup vs baseline: 1.6745x; 1.0740x over previous
#include <cuda_runtime.h>
#include <cuda_bf16.h>
#include <mma.h>

#define N_NODES 100000
#define D 128
#define N_EDGES 1600000
#define BATCH 500000
#define LN_EPS 1e-5f
#define SCAN_CHUNK 1024
#define NBLK ((N_NODES + SCAN_CHUNK - 1) / SCAN_CHUNK)   // 98

using namespace nvcuda;

// Scratch (device globals; no allocation allowed)
__device__ __align__(128) float g_h1[N_NODES * D];   // GEMM output
__device__ __align__(128) float g_h2[N_NODES * D];   // LN output
__device__ __align__(128) int2  g_epack[N_EDGES];    // CSR-permuted {col, val}
__device__ int g_eloc[N_EDGES];                      // intra-row slot per edge
__device__ int g_cnt[N_NODES];
__device__ int g_rowptr[N_NODES + 1];
__device__ int g_bsum[NBLK];
__device__ __align__(128) __nv_bfloat16 g_Wh[D * D]; // preconverted W hi
__device__ __align__(128) __nv_bfloat16 g_Wl[D * D]; // preconverted W lo

#define LDA 136
#define LDB 136
#define LDC 132
#define BLK_ROWS 64
#define GEMM_SMEM (128 * LDB * 2 * 2 + BLK_ROWS * LDA * 2 * 2)   // 104448

// ---------------- W pre-conversion (once; removes 1563x redundant convert) ------------
__global__ void wconv_kernel(const float* __restrict__ W) {
    int i = blockIdx.x * blockDim.x + threadIdx.x;
    if (i < D * D) {
        float wv = W[i];
        __nv_bfloat16 whi = __float2bfloat16(wv);
        g_Wh[i] = whi;
        g_Wl[i] = __float2bfloat16(wv - __bfloat162float(whi));
    }
}

// ---------------- GEMM: h1 = emb @ W + bias (bf16 hi/lo split, 3 MMAs) ----------------
__global__ void gemm_kernel(const float* __restrict__ emb,
                            const float* __restrict__ bias) {
    extern __shared__ __nv_bfloat16 smem[];
    __nv_bfloat16* sWh = smem;
    __nv_bfloat16* sWl = sWh + 128 * LDB;
    __nv_bfloat16* sAh = sWl + 128 * LDB;
    __nv_bfloat16* sAl = sAh + BLK_ROWS * LDA;
    float* sC = (float*)sAh;    // reuse A area (64*132*4 = 33792 <= 34816)

    int tid = threadIdx.x;
    int wid = tid >> 5;
    int wr = wid >> 1;
    int wc = wid & 1;
    int block_row = blockIdx.x * BLK_ROWS;

    // W smem fill: vectorized copy of preconverted bf16 (row = 256B = 16 uint4;
    // LDB stride = 272B, 16B-aligned)
    for (int i = tid; i < 128 * 16; i += 256) {
        int r = i >> 4, q = i & 15;
        ((uint4*)(sWh + r * LDB))[q] = ((const uint4*)(g_Wh + r * D))[q];
        ((uint4*)(sWl + r * LDB))[q] = ((const uint4*)(g_Wl + r * D))[q];
    }
    // A fill: float4 loads + on-the-fly hi/lo split, bfloat162 stores
    for (int i = tid; i < BLK_ROWS * 32; i += 256) {
        int r = i >> 5, c4 = i & 31;
        int grow = block_row + r;
        float4 a = make_float4(0.f, 0.f, 0.f, 0.f);
        if (grow < N_NODES) a = ((const float4*)(emb + (size_t)grow * D))[c4];
        __nv_bfloat16 h0 = __float2bfloat16(a.x), h1 = __float2bfloat16(a.y);
        __nv_bfloat16 h2 = __float2bfloat16(a.z), h3 = __float2bfloat16(a.w);
        __nv_bfloat16 l0 = __float2bfloat16(a.x - __bfloat162float(h0));
        __nv_bfloat16 l1 = __float2bfloat16(a.y - __bfloat162float(h1));
        __nv_bfloat16 l2 = __float2bfloat16(a.z - __bfloat162float(h2));
        __nv_bfloat16 l3 = __float2bfloat16(a.w - __bfloat162float(h3));
        __nv_bfloat162* ph = (__nv_bfloat162*)(sAh + r * LDA);
        __nv_bfloat162* pl = (__nv_bfloat162*)(sAl + r * LDA);
        ph[c4 * 2]     = __nv_bfloat162(h0, h1);
        ph[c4 * 2 + 1] = __nv_bfloat162(h2, h3);
        pl[c4 * 2]     = __nv_bfloat162(l0, l1);
        pl[c4 * 2 + 1] = __nv_bfloat162(l2, l3);
    }
    __syncthreads();

    wmma::fragment<wmma::accumulator, 16, 16, 16, float> acc[4];
    #pragma unroll
    for (int c = 0; c < 4; c++) wmma::fill_fragment(acc[c], 0.f);

    #pragma unroll
    for (int k = 0; k < 8; k++) {
        wmma::fragment<wmma::matrix_a, 16, 16, 16, __nv_bfloat16, wmma::row_major> ah, al;
        wmma::load_matrix_sync(ah, sAh + wr * 16 * LDA + k * 16, LDA);
        wmma::load_matrix_sync(al, sAl + wr * 16 * LDA + k * 16, LDA);
        #pragma unroll
        for (int c = 0; c < 4; c++) {
            int cc = wc * 64 + c * 16;
            wmma::fragment<wmma::matrix_b, 16, 16, 16, __nv_bfloat16, wmma::row_major> bh, bl;
            wmma::load_matrix_sync(bh, sWh + k * 16 * LDB + cc, LDB);
            wmma::load_matrix_sync(bl, sWl + k * 16 * LDB + cc, LDB);
            wmma::mma_sync(acc[c], ah, bh, acc[c]);
            wmma::mma_sync(acc[c], ah, bl, acc[c]);
            wmma::mma_sync(acc[c], al, bh, acc[c]);
        }
    }
    __syncthreads();
    #pragma unroll
    for (int c = 0; c < 4; c++)
        wmma::store_matrix_sync(sC + wr * 16 * LDC + wc * 64 + c * 16, acc[c],
                                LDC, wmma::mem_row_major);
    __syncthreads();

    // epilogue: vectorized bias + store (LDC stride = 528B, 16B-aligned)
    for (int i = tid; i < BLK_ROWS * 32; i += 256) {
        int r = i >> 5, c4 = i & 31;
        int grow = block_row + r;
        if (grow < N_NODES) {
            float4 cv = ((const float4*)(sC + r * LDC))[c4];
            float4 bv = ((const float4*)bias)[c4];
            cv.x += bv.x; cv.y += bv.y; cv.z += bv.z; cv.w += bv.w;
            ((float4*)(g_h1 + (size_t)grow * D))[c4] = cv;
        }
    }
}

// ---------------- CSR build ----------------
__global__ void zero_cnt_kernel() {
    int i = blockIdx.x * blockDim.x + threadIdx.x;
    if (i < N_NODES) g_cnt[i] = 0;
}

// histogram + record intra-row slot (single atomic pass over edges)
__global__ void hist_kernel(const int* __restrict__ rows) {
    int e = blockIdx.x * blockDim.x + threadIdx.x;
    if (e < N_EDGES) g_eloc[e] = atomicAdd(&g_cnt[rows[e]], 1);
}

__global__ void scanA_kernel() {
    __shared__ int s[SCAN_CHUNK];
    int tid = threadIdx.x;
    int idx = blockIdx.x * SCAN_CHUNK + tid;
    s[tid] = (idx < N_NODES) ? g_cnt[idx] : 0;
    __syncthreads();
    #pragma unroll
    for (int off = 1; off < SCAN_CHUNK; off <<= 1) {
        int t = (tid >= off) ? s[tid - off] : 0;
        __syncthreads();
        s[tid] += t;
        __syncthreads();
    }
    if (idx < N_NODES) g_rowptr[idx + 1] = s[tid];
    if (tid == SCAN_CHUNK - 1) g_bsum[blockIdx.x] = s[tid];
}

__global__ void scanB_kernel() {
    __shared__ int s[NBLK];
    int tid = threadIdx.x;
    if (tid < NBLK) s[tid] = g_bsum[tid];
    __syncthreads();
    if (tid == 0) {
        int acc = 0;
        #pragma unroll 1
        for (int i = 0; i < NBLK; i++) { int t = s[i]; s[i] = acc; acc += t; }
    }
    __syncthreads();
    if (tid < NBLK) g_bsum[tid] = s[tid];
}

__global__ void scanC_kernel() {
    int idx = blockIdx.x * SCAN_CHUNK + threadIdx.x;
    if (idx < N_NODES) g_rowptr[idx + 1] += g_bsum[blockIdx.x];
    if (idx == 0) g_rowptr[0] = 0;
}

// pure computed store — no atomics
__global__ void scatter_kernel(const float* __restrict__ vals,
                               const int* __restrict__ rows,
                               const int* __restrict__ cols) {
    int e = blockIdx.x * blockDim.x + threadIdx.x;
    if (e >= N_EDGES) return;
    int p = g_rowptr[rows[e]] + g_eloc[e];
    g_epack[p] = make_int2(cols[e], __float_as_int(vals[e]));
}

// ---------------- fused SpMM + ReLU + LayerNorm: one warp per row ----------------
__global__ void spmm_ln_kernel(const float* __restrict__ gamma,
                               const float* __restrict__ beta) {
    int row = blockIdx.x * 4 + (threadIdx.x >> 5);
    if (row >= N_NODES) return;
    int lane = threadIdx.x & 31;
    int s = g_rowptr[row];
    int e = g_rowptr[row + 1];

    float4 acc = make_float4(0.f, 0.f, 0.f, 0.f);
    for (int base = s; base < e; base += 32) {
        int n = min(32, e - base);
        int2 ev = make_int2(0, 0);
        if (base + lane < e) ev = g_epack[base + lane];
        int j = 0;
        for (; j + 4 <= n; j += 4) {
            int c0 = __shfl_sync(0xffffffffu, ev.x, j);
            int c1 = __shfl_sync(0xffffffffu, ev.x, j + 1);
            int c2 = __shfl_sync(0xffffffffu, ev.x, j + 2);
            int c3 = __shfl_sync(0xffffffffu, ev.x, j + 3);
            float v0 = __int_as_float(__shfl_sync(0xffffffffu, ev.y, j));
            float v1 = __int_as_float(__shfl_sync(0xffffffffu, ev.y, j + 1));
            float v2 = __int_as_float(__shfl_sync(0xffffffffu, ev.y, j + 2));
            float v3 = __int_as_float(__shfl_sync(0xffffffffu, ev.y, j + 3));
            float4 m0 = ((const float4*)(g_h1 + (size_t)c0 * D))[lane];
            float4 m1 = ((const float4*)(g_h1 + (size_t)c1 * D))[lane];
            float4 m2 = ((const float4*)(g_h1 + (size_t)c2 * D))[lane];
            float4 m3 = ((const float4*)(g_h1 + (size_t)c3 * D))[lane];
            acc.x = fmaf(v0, m0.x, acc.x); acc.y = fmaf(v0, m0.y, acc.y);
            acc.z = fmaf(v0, m0.z, acc.z); acc.w = fmaf(v0, m0.w, acc.w);
            acc.x = fmaf(v1, m1.x, acc.x); acc.y = fmaf(v1, m1.y, acc.y);
            acc.z = fmaf(v1, m1.z, acc.z); acc.w = fmaf(v1, m1.w, acc.w);
            acc.x = fmaf(v2, m2.x, acc.x); acc.y = fmaf(v2, m2.y, acc.y);
            acc.z = fmaf(v2, m2.z, acc.z); acc.w = fmaf(v2, m2.w, acc.w);
            acc.x = fmaf(v3, m3.x, acc.x); acc.y = fmaf(v3, m3.y, acc.y);
            acc.z = fmaf(v3, m3.z, acc.z); acc.w = fmaf(v3, m3.w, acc.w);
        }
        for (; j < n; j++) {
            int   c = __shfl_sync(0xffffffffu, ev.x, j);
            float v = __int_as_float(__shfl_sync(0xffffffffu, ev.y, j));
            float4 m = ((const float4*)(g_h1 + (size_t)c * D))[lane];
            acc.x = fmaf(v, m.x, acc.x); acc.y = fmaf(v, m.y, acc.y);
            acc.z = fmaf(v, m.z, acc.z); acc.w = fmaf(v, m.w, acc.w);
        }
    }

    acc.x = fmaxf(acc.x, 0.f); acc.y = fmaxf(acc.y, 0.f);
    acc.z = fmaxf(acc.z, 0.f); acc.w = fmaxf(acc.w, 0.f);

    float sm = acc.x + acc.y + acc.z + acc.w;
    #pragma unroll
    for (int o = 16; o; o >>= 1) sm += __shfl_xor_sync(0xffffffffu, sm, o);
    float mu = sm * (1.f / 128.f);

    float dx = acc.x - mu, dy = acc.y - mu, dz = acc.z - mu, dw = acc.w - mu;
    float q = dx * dx + dy * dy + dz * dz + dw * dw;
    #pragma unroll
    for (int o = 16; o; o >>= 1) q += __shfl_xor_sync(0xffffffffu, q, o);
    float rs = rsqrtf(q * (1.f / 128.f) + LN_EPS);

    float4 g = ((const float4*)gamma)[lane];
    float4 b = ((const float4*)beta)[lane];
    float4 o;
    o.x = dx * rs * g.x + b.x;
    o.y = dy * rs * g.y + b.y;
    o.z = dz * rs * g.z + b.z;
    o.w = dw * rs * g.w + b.w;
    ((float4*)(g_h2 + (size_t)row * D))[lane] = o;
}

// ---------------- masked batch gather: 2 rows per warp ----------------
__global__ void gather_kernel(const int* __restrict__ x, float* __restrict__ out) {
    int b0 = (blockIdx.x * 8 + (threadIdx.x >> 5)) * 2;
    if (b0 >= BATCH) return;
    int lane = threadIdx.x & 31;

    int x0 = x[b0];
    int x1 = (b0 + 1 < BATCH) ? x[b0 + 1] : 0;
    float4 o0 = make_float4(0.f, 0.f, 0.f, 0.f);
    float4 o1 = o0;
    if (x0 >= 1 && x0 <= N_NODES)
        o0 = ((const float4*)(g_h2 + (size_t)(x0 - 1) * D))[lane];
    if (x1 >= 1 && x1 <= N_NODES)
        o1 = ((const float4*)(g_h2 + (size_t)(x1 - 1) * D))[lane];
    ((float4*)(out + (size_t)b0 * D))[lane] = o0;
    if (b0 + 1 < BATCH)
        ((float4*)(out + (size_t)(b0 + 1) * D))[lane] = o1;
}

extern "C" void kernel_launch(void* const* d_in, const int* in_sizes, int n_in,
                              void* d_out, int out_size) {
    const int*   x     = (const int*)d_in[0];
    const float* emb   = (const float*)d_in[1];
    const float* W     = (const float*)d_in[2];
    const float* bias  = (const float*)d_in[3];
    const float* vals  = (const float*)d_in[4];
    const int*   rows  = (const int*)d_in[5];
    const int*   cols  = (const int*)d_in[6];
    const float* gamma = (const float*)d_in[7];
    const float* beta  = (const float*)d_in[8];
    float* out = (float*)d_out;

    cudaFuncSetAttribute(gemm_kernel, cudaFuncAttributeMaxDynamicSharedMemorySize, GEMM_SMEM);

    wconv_kernel<<<(D * D + 255) / 256, 256>>>(W);
    gemm_kernel<<<(N_NODES + BLK_ROWS - 1) / BLK_ROWS, 256, GEMM_SMEM>>>(emb, bias);
    zero_cnt_kernel<<<(N_NODES + 255) / 256, 256>>>();
    hist_kernel<<<(N_EDGES + 255) / 256, 256>>>(rows);
    scanA_kernel<<<NBLK, SCAN_CHUNK>>>();
    scanB_kernel<<<1, 128>>>();
    scanC_kernel<<<NBLK, SCAN_CHUNK>>>();
    scatter_kernel<<<(N_EDGES + 255) / 256, 256>>>(vals, rows, cols);
    spmm_ln_kernel<<<(N_NODES + 3) / 4, 128>>>(gamma, beta);
    gather_kernel<<<(BATCH + 15) / 16, 256>>>(x, out);
}

// round 7
// speedup vs baseline: 1.6798x; 1.0032x over previous
#include <cuda_runtime.h>
#include <cuda_bf16.h>
#include <mma.h>

#define N_NODES 100000
#define D 128
#define N_EDGES 1600000
#define BATCH 500000
#define LN_EPS 1e-5f
#define SCAN_CHUNK 1024
#define NBLK ((N_NODES + SCAN_CHUNK - 1) / SCAN_CHUNK)   // 98

using namespace nvcuda;

// Scratch (device globals; no allocation allowed)
__device__ __align__(128) float g_h1[N_NODES * D];   // GEMM output
__device__ __align__(128) float g_h2[N_NODES * D];   // LN output
__device__ __align__(128) int2  g_epack[N_EDGES];    // CSR-permuted {col, val}
__device__ int g_eloc[N_EDGES];                      // intra-row slot per edge
__device__ int g_cnt[N_NODES];
__device__ int g_rowptr[N_NODES + 1];
__device__ int g_bsum[NBLK];
__device__ __align__(128) __nv_bfloat16 g_Wh[D * D];
__device__ __align__(128) __nv_bfloat16 g_Wl[D * D];

#define LDA 136
#define LDB 136
#define LDC 132
#define BLK_ROWS 64
#define GEMM_SMEM (128 * LDB * 2 * 2 + BLK_ROWS * LDA * 2 * 2)   // 104448

// ---------------- W pre-conversion (once) ----------------
__global__ void wconv_kernel(const float* __restrict__ W) {
    int i = blockIdx.x * blockDim.x + threadIdx.x;
    if (i < D * D) {
        float wv = W[i];
        __nv_bfloat16 whi = __float2bfloat16(wv);
        g_Wh[i] = whi;
        g_Wl[i] = __float2bfloat16(wv - __bfloat162float(whi));
    }
}

// ---------------- GEMM: h1 = emb @ W + bias (bf16 hi/lo split, 3 MMAs) ----------------
__global__ void gemm_kernel(const float* __restrict__ emb,
                            const float* __restrict__ bias) {
    extern __shared__ __nv_bfloat16 smem[];
    __nv_bfloat16* sWh = smem;
    __nv_bfloat16* sWl = sWh + 128 * LDB;
    __nv_bfloat16* sAh = sWl + 128 * LDB;
    __nv_bfloat16* sAl = sAh + BLK_ROWS * LDA;
    float* sC = (float*)sAh;

    int tid = threadIdx.x;
    int wid = tid >> 5;
    int wr = wid >> 1;
    int wc = wid & 1;
    int block_row = blockIdx.x * BLK_ROWS;

    for (int i = tid; i < 128 * 16; i += 256) {
        int r = i >> 4, q = i & 15;
        ((uint4*)(sWh + r * LDB))[q] = ((const uint4*)(g_Wh + r * D))[q];
        ((uint4*)(sWl + r * LDB))[q] = ((const uint4*)(g_Wl + r * D))[q];
    }
    for (int i = tid; i < BLK_ROWS * 32; i += 256) {
        int r = i >> 5, c4 = i & 31;
        int grow = block_row + r;
        float4 a = make_float4(0.f, 0.f, 0.f, 0.f);
        if (grow < N_NODES) a = ((const float4*)(emb + (size_t)grow * D))[c4];
        __nv_bfloat16 h0 = __float2bfloat16(a.x), h1 = __float2bfloat16(a.y);
        __nv_bfloat16 h2 = __float2bfloat16(a.z), h3 = __float2bfloat16(a.w);
        __nv_bfloat16 l0 = __float2bfloat16(a.x - __bfloat162float(h0));
        __nv_bfloat16 l1 = __float2bfloat16(a.y - __bfloat162float(h1));
        __nv_bfloat16 l2 = __float2bfloat16(a.z - __bfloat162float(h2));
        __nv_bfloat16 l3 = __float2bfloat16(a.w - __bfloat162float(h3));
        __nv_bfloat162* ph = (__nv_bfloat162*)(sAh + r * LDA);
        __nv_bfloat162* pl = (__nv_bfloat162*)(sAl + r * LDA);
        ph[c4 * 2]     = __nv_bfloat162(h0, h1);
        ph[c4 * 2 + 1] = __nv_bfloat162(h2, h3);
        pl[c4 * 2]     = __nv_bfloat162(l0, l1);
        pl[c4 * 2 + 1] = __nv_bfloat162(l2, l3);
    }
    __syncthreads();

    wmma::fragment<wmma::accumulator, 16, 16, 16, float> acc[4];
    #pragma unroll
    for (int c = 0; c < 4; c++) wmma::fill_fragment(acc[c], 0.f);

    #pragma unroll
    for (int k = 0; k < 8; k++) {
        wmma::fragment<wmma::matrix_a, 16, 16, 16, __nv_bfloat16, wmma::row_major> ah, al;
        wmma::load_matrix_sync(ah, sAh + wr * 16 * LDA + k * 16, LDA);
        wmma::load_matrix_sync(al, sAl + wr * 16 * LDA + k * 16, LDA);
        #pragma unroll
        for (int c = 0; c < 4; c++) {
            int cc = wc * 64 + c * 16;
            wmma::fragment<wmma::matrix_b, 16, 16, 16, __nv_bfloat16, wmma::row_major> bh, bl;
            wmma::load_matrix_sync(bh, sWh + k * 16 * LDB + cc, LDB);
            wmma::load_matrix_sync(bl, sWl + k * 16 * LDB + cc, LDB);
            wmma::mma_sync(acc[c], ah, bh, acc[c]);
            wmma::mma_sync(acc[c], ah, bl, acc[c]);
            wmma::mma_sync(acc[c], al, bh, acc[c]);
        }
    }
    __syncthreads();
    #pragma unroll
    for (int c = 0; c < 4; c++)
        wmma::store_matrix_sync(sC + wr * 16 * LDC + wc * 64 + c * 16, acc[c],
                                LDC, wmma::mem_row_major);
    __syncthreads();

    for (int i = tid; i < BLK_ROWS * 32; i += 256) {
        int r = i >> 5, c4 = i & 31;
        int grow = block_row + r;
        if (grow < N_NODES) {
            float4 cv = ((const float4*)(sC + r * LDC))[c4];
            float4 bv = ((const float4*)bias)[c4];
            cv.x += bv.x; cv.y += bv.y; cv.z += bv.z; cv.w += bv.w;
            ((float4*)(g_h1 + (size_t)grow * D))[c4] = cv;
        }
    }
}

// ---------------- CSR build ----------------
__global__ void zero_cnt_kernel() {
    int i = blockIdx.x * blockDim.x + threadIdx.x;
    if (i < N_NODES) g_cnt[i] = 0;
}

__global__ void hist_kernel(const int* __restrict__ rows) {
    int e = blockIdx.x * blockDim.x + threadIdx.x;
    if (e < N_EDGES) g_eloc[e] = atomicAdd(&g_cnt[rows[e]], 1);
}

__global__ void scanA_kernel() {
    __shared__ int s[SCAN_CHUNK];
    int tid = threadIdx.x;
    int idx = blockIdx.x * SCAN_CHUNK + tid;
    s[tid] = (idx < N_NODES) ? g_cnt[idx] : 0;
    __syncthreads();
    #pragma unroll
    for (int off = 1; off < SCAN_CHUNK; off <<= 1) {
        int t = (tid >= off) ? s[tid - off] : 0;
        __syncthreads();
        s[tid] += t;
        __syncthreads();
    }
    if (idx < N_NODES) g_rowptr[idx + 1] = s[tid];
    if (tid == SCAN_CHUNK - 1) g_bsum[blockIdx.x] = s[tid];
}

__global__ void scanB_kernel() {
    __shared__ int s[NBLK];
    int tid = threadIdx.x;
    if (tid < NBLK) s[tid] = g_bsum[tid];
    __syncthreads();
    if (tid == 0) {
        int acc = 0;
        #pragma unroll 1
        for (int i = 0; i < NBLK; i++) { int t = s[i]; s[i] = acc; acc += t; }
    }
    __syncthreads();
    if (tid < NBLK) g_bsum[tid] = s[tid];
}

__global__ void scanC_kernel() {
    int idx = blockIdx.x * SCAN_CHUNK + threadIdx.x;
    if (idx < N_NODES) g_rowptr[idx + 1] += g_bsum[blockIdx.x];
    if (idx == 0) g_rowptr[0] = 0;
}

__global__ void scatter_kernel(const float* __restrict__ vals,
                               const int* __restrict__ rows,
                               const int* __restrict__ cols) {
    int e = blockIdx.x * blockDim.x + threadIdx.x;
    if (e >= N_EDGES) return;
    int p = g_rowptr[rows[e]] + g_eloc[e];
    g_epack[p] = make_int2(cols[e], __float_as_int(vals[e]));
}

// ---------------- fused SpMM + ReLU + LayerNorm: one warp per row, MLP=8 ----------------
__global__ void spmm_ln_kernel(const float* __restrict__ gamma,
                               const float* __restrict__ beta) {
    int row = blockIdx.x * 8 + (threadIdx.x >> 5);
    if (row >= N_NODES) return;
    int lane = threadIdx.x & 31;
    int s = g_rowptr[row];
    int e = g_rowptr[row + 1];

    float4 acc = make_float4(0.f, 0.f, 0.f, 0.f);
    for (int base = s; base < e; base += 32) {
        int n = min(32, e - base);
        int2 ev = make_int2(0, 0);
        if (base + lane < e) ev = g_epack[base + lane];
        int j = 0;
        for (; j + 8 <= n; j += 8) {
            float v[8]; float4 m[8];
            #pragma unroll
            for (int u = 0; u < 8; u++) {
                int c = __shfl_sync(0xffffffffu, ev.x, j + u);
                v[u] = __int_as_float(__shfl_sync(0xffffffffu, ev.y, j + u));
                m[u] = ((const float4*)(g_h1 + (size_t)c * D))[lane];
            }
            #pragma unroll
            for (int u = 0; u < 8; u++) {
                acc.x = fmaf(v[u], m[u].x, acc.x);
                acc.y = fmaf(v[u], m[u].y, acc.y);
                acc.z = fmaf(v[u], m[u].z, acc.z);
                acc.w = fmaf(v[u], m[u].w, acc.w);
            }
        }
        for (; j + 4 <= n; j += 4) {
            float v[4]; float4 m[4];
            #pragma unroll
            for (int u = 0; u < 4; u++) {
                int c = __shfl_sync(0xffffffffu, ev.x, j + u);
                v[u] = __int_as_float(__shfl_sync(0xffffffffu, ev.y, j + u));
                m[u] = ((const float4*)(g_h1 + (size_t)c * D))[lane];
            }
            #pragma unroll
            for (int u = 0; u < 4; u++) {
                acc.x = fmaf(v[u], m[u].x, acc.x);
                acc.y = fmaf(v[u], m[u].y, acc.y);
                acc.z = fmaf(v[u], m[u].z, acc.z);
                acc.w = fmaf(v[u], m[u].w, acc.w);
            }
        }
        for (; j < n; j++) {
            int   c = __shfl_sync(0xffffffffu, ev.x, j);
            float v = __int_as_float(__shfl_sync(0xffffffffu, ev.y, j));
            float4 m = ((const float4*)(g_h1 + (size_t)c * D))[lane];
            acc.x = fmaf(v, m.x, acc.x); acc.y = fmaf(v, m.y, acc.y);
            acc.z = fmaf(v, m.z, acc.z); acc.w = fmaf(v, m.w, acc.w);
        }
    }

    acc.x = fmaxf(acc.x, 0.f); acc.y = fmaxf(acc.y, 0.f);
    acc.z = fmaxf(acc.z, 0.f); acc.w = fmaxf(acc.w, 0.f);

    float sm = acc.x + acc.y + acc.z + acc.w;
    #pragma unroll
    for (int o = 16; o; o >>= 1) sm += __shfl_xor_sync(0xffffffffu, sm, o);
    float mu = sm * (1.f / 128.f);

    float dx = acc.x - mu, dy = acc.y - mu, dz = acc.z - mu, dw = acc.w - mu;
    float q = dx * dx + dy * dy + dz * dz + dw * dw;
    #pragma unroll
    for (int o = 16; o; o >>= 1) q += __shfl_xor_sync(0xffffffffu, q, o);
    float rs = rsqrtf(q * (1.f / 128.f) + LN_EPS);

    float4 g = ((const float4*)gamma)[lane];
    float4 b = ((const float4*)beta)[lane];
    float4 o;
    o.x = dx * rs * g.x + b.x;
    o.y = dy * rs * g.y + b.y;
    o.z = dz * rs * g.z + b.z;
    o.w = dw * rs * g.w + b.w;
    ((float4*)(g_h2 + (size_t)row * D))[lane] = o;
}

// ---------------- masked batch gather: 4 rows/warp, streaming stores ----------------
// BATCH % 4 == 0, so each warp owns exactly 4 rows (no guards).
__global__ void gather_kernel(const int* __restrict__ x, float* __restrict__ out) {
    int w = blockIdx.x * 8 + (threadIdx.x >> 5);
    int b0 = w * 4;
    if (b0 >= BATCH) return;
    int lane = threadIdx.x & 31;

    int xi[4];
    #pragma unroll
    for (int u = 0; u < 4; u++) xi[u] = x[b0 + u];

    float4 o[4];
    #pragma unroll
    for (int u = 0; u < 4; u++) {
        o[u] = make_float4(0.f, 0.f, 0.f, 0.f);
        if (xi[u] >= 1 && xi[u] <= N_NODES)
            o[u] = ((const float4*)(g_h2 + (size_t)(xi[u] - 1) * D))[lane];
    }
    #pragma unroll
    for (int u = 0; u < 4; u++)
        __stcs((float4*)(out + (size_t)(b0 + u) * D) + lane, o[u]);
}

extern "C" void kernel_launch(void* const* d_in, const int* in_sizes, int n_in,
                              void* d_out, int out_size) {
    const int*   x     = (const int*)d_in[0];
    const float* emb   = (const float*)d_in[1];
    const float* W     = (const float*)d_in[2];
    const float* bias  = (const float*)d_in[3];
    const float* vals  = (const float*)d_in[4];
    const int*   rows  = (const int*)d_in[5];
    const int*   cols  = (const int*)d_in[6];
    const float* gamma = (const float*)d_in[7];
    const float* beta  = (const float*)d_in[8];
    float* out = (float*)d_out;

    // Lazily-created side stream + fork/join events (host resources, created once,
    // outside any capture; the captured graph is identical on every call).
    static cudaStream_t s2 = nullptr;
    static cudaEvent_t evFork = nullptr, evJoin = nullptr;
    if (s2 == nullptr) {
        cudaStreamCreateWithFlags(&s2, cudaStreamNonBlocking);
        cudaEventCreateWithFlags(&evFork, cudaEventDisableTiming);
        cudaEventCreateWithFlags(&evJoin, cudaEventDisableTiming);
    }

    cudaFuncSetAttribute(gemm_kernel, cudaFuncAttributeMaxDynamicSharedMemorySize, GEMM_SMEM);

    // fork: CSR build chain runs concurrently with wconv+gemm
    cudaEventRecord(evFork, 0);
    cudaStreamWaitEvent(s2, evFork, 0);

    zero_cnt_kernel<<<(N_NODES + 255) / 256, 256, 0, s2>>>();
    hist_kernel<<<(N_EDGES + 255) / 256, 256, 0, s2>>>(rows);
    scanA_kernel<<<NBLK, SCAN_CHUNK, 0, s2>>>();
    scanB_kernel<<<1, 128, 0, s2>>>();
    scanC_kernel<<<NBLK, SCAN_CHUNK, 0, s2>>>();
    scatter_kernel<<<(N_EDGES + 255) / 256, 256, 0, s2>>>(vals, rows, cols);

    wconv_kernel<<<(D * D + 255) / 256, 256>>>(W);
    gemm_kernel<<<(N_NODES + BLK_ROWS - 1) / BLK_ROWS, 256, GEMM_SMEM>>>(emb, bias);

    // join
    cudaEventRecord(evJoin, s2);
    cudaStreamWaitEvent(0, evJoin, 0);

    spmm_ln_kernel<<<(N_NODES + 7) / 8, 256>>>(gamma, beta);
    gather_kernel<<<(BATCH / 4 + 7) / 8, 256>>>(x, out);
}

// round 8
// speedup vs baseline: 1.8898x; 1.1250x over previous
#include <cuda_runtime.h>
#include <cuda_bf16.h>
#include <cuda_fp16.h>
#include <mma.h>

#define N_NODES 100000
#define D 128
#define N_EDGES 1600000
#define BATCH 500000
#define LN_EPS 1e-5f
#define SCAN_CHUNK 1024
#define NBLK ((N_NODES + SCAN_CHUNK - 1) / SCAN_CHUNK)   // 98

using namespace nvcuda;

// Scratch (device globals; no allocation allowed)
__device__ __align__(128) __half g_h1h[N_NODES * D]; // GEMM output (fp16 storage)
__device__ __align__(128) float g_h2[N_NODES * D];   // LN output (fp32)
__device__ __align__(128) int2  g_epack[N_EDGES];    // CSR-permuted {col, val}
__device__ int g_eloc[N_EDGES];
__device__ int g_cnt[N_NODES];
__device__ int g_rowptr[N_NODES + 1];
__device__ int g_bsum[NBLK];
__device__ __align__(128) __nv_bfloat16 g_Wh[D * D];
__device__ __align__(128) __nv_bfloat16 g_Wl[D * D];

#define LDA 136
#define LDB 136
#define LDC 132
#define BLK_ROWS 64
#define GEMM_SMEM (128 * LDB * 2 * 2 + BLK_ROWS * LDA * 2 * 2)   // 104448

// ---------------- W pre-conversion (once) ----------------
__global__ void wconv_kernel(const float* __restrict__ W) {
    int i = blockIdx.x * blockDim.x + threadIdx.x;
    if (i < D * D) {
        float wv = W[i];
        __nv_bfloat16 whi = __float2bfloat16(wv);
        g_Wh[i] = whi;
        g_Wl[i] = __float2bfloat16(wv - __bfloat162float(whi));
    }
}

// ---------------- GEMM: h1 = emb @ W + bias (bf16 hi/lo, fp32 accum, fp16 store) ------
__global__ void gemm_kernel(const float* __restrict__ emb,
                            const float* __restrict__ bias) {
    extern __shared__ __nv_bfloat16 smem[];
    __nv_bfloat16* sWh = smem;
    __nv_bfloat16* sWl = sWh + 128 * LDB;
    __nv_bfloat16* sAh = sWl + 128 * LDB;
    __nv_bfloat16* sAl = sAh + BLK_ROWS * LDA;
    float* sC = (float*)sAh;

    int tid = threadIdx.x;
    int wid = tid >> 5;
    int wr = wid >> 1;
    int wc = wid & 1;
    int block_row = blockIdx.x * BLK_ROWS;

    for (int i = tid; i < 128 * 16; i += 256) {
        int r = i >> 4, q = i & 15;
        ((uint4*)(sWh + r * LDB))[q] = ((const uint4*)(g_Wh + r * D))[q];
        ((uint4*)(sWl + r * LDB))[q] = ((const uint4*)(g_Wl + r * D))[q];
    }
    for (int i = tid; i < BLK_ROWS * 32; i += 256) {
        int r = i >> 5, c4 = i & 31;
        int grow = block_row + r;
        float4 a = make_float4(0.f, 0.f, 0.f, 0.f);
        if (grow < N_NODES) a = ((const float4*)(emb + (size_t)grow * D))[c4];
        __nv_bfloat16 h0 = __float2bfloat16(a.x), h1 = __float2bfloat16(a.y);
        __nv_bfloat16 h2 = __float2bfloat16(a.z), h3 = __float2bfloat16(a.w);
        __nv_bfloat16 l0 = __float2bfloat16(a.x - __bfloat162float(h0));
        __nv_bfloat16 l1 = __float2bfloat16(a.y - __bfloat162float(h1));
        __nv_bfloat16 l2 = __float2bfloat16(a.z - __bfloat162float(h2));
        __nv_bfloat16 l3 = __float2bfloat16(a.w - __bfloat162float(h3));
        __nv_bfloat162* ph = (__nv_bfloat162*)(sAh + r * LDA);
        __nv_bfloat162* pl = (__nv_bfloat162*)(sAl + r * LDA);
        ph[c4 * 2]     = __nv_bfloat162(h0, h1);
        ph[c4 * 2 + 1] = __nv_bfloat162(h2, h3);
        pl[c4 * 2]     = __nv_bfloat162(l0, l1);
        pl[c4 * 2 + 1] = __nv_bfloat162(l2, l3);
    }
    __syncthreads();

    wmma::fragment<wmma::accumulator, 16, 16, 16, float> acc[4];
    #pragma unroll
    for (int c = 0; c < 4; c++) wmma::fill_fragment(acc[c], 0.f);

    #pragma unroll
    for (int k = 0; k < 8; k++) {
        wmma::fragment<wmma::matrix_a, 16, 16, 16, __nv_bfloat16, wmma::row_major> ah, al;
        wmma::load_matrix_sync(ah, sAh + wr * 16 * LDA + k * 16, LDA);
        wmma::load_matrix_sync(al, sAl + wr * 16 * LDA + k * 16, LDA);
        #pragma unroll
        for (int c = 0; c < 4; c++) {
            int cc = wc * 64 + c * 16;
            wmma::fragment<wmma::matrix_b, 16, 16, 16, __nv_bfloat16, wmma::row_major> bh, bl;
            wmma::load_matrix_sync(bh, sWh + k * 16 * LDB + cc, LDB);
            wmma::load_matrix_sync(bl, sWl + k * 16 * LDB + cc, LDB);
            wmma::mma_sync(acc[c], ah, bh, acc[c]);
            wmma::mma_sync(acc[c], ah, bl, acc[c]);
            wmma::mma_sync(acc[c], al, bh, acc[c]);
        }
    }
    __syncthreads();
    #pragma unroll
    for (int c = 0; c < 4; c++)
        wmma::store_matrix_sync(sC + wr * 16 * LDC + wc * 64 + c * 16, acc[c],
                                LDC, wmma::mem_row_major);
    __syncthreads();

    // epilogue: bias add in fp32, single fp16 rounding on store
    for (int i = tid; i < BLK_ROWS * 32; i += 256) {
        int r = i >> 5, c4 = i & 31;
        int grow = block_row + r;
        if (grow < N_NODES) {
            float4 cv = ((const float4*)(sC + r * LDC))[c4];
            float4 bv = ((const float4*)bias)[c4];
            __half2* p = (__half2*)(g_h1h + (size_t)grow * D);
            p[c4 * 2]     = __floats2half2_rn(cv.x + bv.x, cv.y + bv.y);
            p[c4 * 2 + 1] = __floats2half2_rn(cv.z + bv.z, cv.w + bv.w);
        }
    }
}

// ---------------- CSR build ----------------
__global__ void zero_cnt_kernel() {
    int i = blockIdx.x * blockDim.x + threadIdx.x;
    if (i < N_NODES) g_cnt[i] = 0;
}

__global__ void hist_kernel(const int* __restrict__ rows) {
    int e = blockIdx.x * blockDim.x + threadIdx.x;
    if (e < N_EDGES) g_eloc[e] = atomicAdd(&g_cnt[rows[e]], 1);
}

__global__ void scanA_kernel() {
    __shared__ int s[SCAN_CHUNK];
    int tid = threadIdx.x;
    int idx = blockIdx.x * SCAN_CHUNK + tid;
    s[tid] = (idx < N_NODES) ? g_cnt[idx] : 0;
    __syncthreads();
    #pragma unroll
    for (int off = 1; off < SCAN_CHUNK; off <<= 1) {
        int t = (tid >= off) ? s[tid - off] : 0;
        __syncthreads();
        s[tid] += t;
        __syncthreads();
    }
    if (idx < N_NODES) g_rowptr[idx + 1] = s[tid];
    if (tid == SCAN_CHUNK - 1) g_bsum[blockIdx.x] = s[tid];
}

// warp/shared shfl scan over NBLK=98 block sums (exclusive)
__global__ void scanB_kernel() {
    int tid = threadIdx.x;          // 128 threads
    int lane = tid & 31, w = tid >> 5;
    int v = (tid < NBLK) ? g_bsum[tid] : 0;
    int inc = v;
    #pragma unroll
    for (int off = 1; off < 32; off <<= 1) {
        int t = __shfl_up_sync(0xffffffffu, inc, off);
        if (lane >= off) inc += t;
    }
    __shared__ int ws[4];
    if (lane == 31) ws[w] = inc;
    __syncthreads();
    int add = 0;
    #pragma unroll
    for (int i = 0; i < 4; i++) if (i < w) add += ws[i];
    if (tid < NBLK) g_bsum[tid] = inc + add - v;   // exclusive
}

__global__ void scanC_kernel() {
    int idx = blockIdx.x * SCAN_CHUNK + threadIdx.x;
    if (idx < N_NODES) g_rowptr[idx + 1] += g_bsum[blockIdx.x];
    if (idx == 0) g_rowptr[0] = 0;
}

__global__ void scatter_kernel(const float* __restrict__ vals,
                               const int* __restrict__ rows,
                               const int* __restrict__ cols) {
    int e = blockIdx.x * blockDim.x + threadIdx.x;
    if (e >= N_EDGES) return;
    int p = g_rowptr[rows[e]] + g_eloc[e];
    g_epack[p] = make_int2(cols[e], __float_as_int(vals[e]));
}

// ---------------- fused SpMM + ReLU + LayerNorm: warp/row, fp16 gathers ----------------
// Lane l covers features [4l, 4l+4): loads uint2 (4 halfs) per edge.
__global__ void spmm_ln_kernel(const float* __restrict__ gamma,
                               const float* __restrict__ beta) {
    int row = blockIdx.x * 8 + (threadIdx.x >> 5);
    if (row >= N_NODES) return;
    int lane = threadIdx.x & 31;
    int s = g_rowptr[row];
    int e = g_rowptr[row + 1];

    float4 acc = make_float4(0.f, 0.f, 0.f, 0.f);
    for (int base = s; base < e; base += 32) {
        int n = min(32, e - base);
        int2 ev = make_int2(0, 0);
        if (base + lane < e) ev = g_epack[base + lane];
        int j = 0;
        for (; j + 8 <= n; j += 8) {
            float v[8]; uint2 m[8];
            #pragma unroll
            for (int u = 0; u < 8; u++) {
                int c = __shfl_sync(0xffffffffu, ev.x, j + u);
                v[u] = __int_as_float(__shfl_sync(0xffffffffu, ev.y, j + u));
                m[u] = ((const uint2*)(g_h1h + (size_t)c * D))[lane];
            }
            #pragma unroll
            for (int u = 0; u < 8; u++) {
                float2 f0 = __half22float2(*(__half2*)&m[u].x);
                float2 f1 = __half22float2(*(__half2*)&m[u].y);
                acc.x = fmaf(v[u], f0.x, acc.x);
                acc.y = fmaf(v[u], f0.y, acc.y);
                acc.z = fmaf(v[u], f1.x, acc.z);
                acc.w = fmaf(v[u], f1.y, acc.w);
            }
        }
        for (; j < n; j++) {
            int   c = __shfl_sync(0xffffffffu, ev.x, j);
            float v = __int_as_float(__shfl_sync(0xffffffffu, ev.y, j));
            uint2 m = ((const uint2*)(g_h1h + (size_t)c * D))[lane];
            float2 f0 = __half22float2(*(__half2*)&m.x);
            float2 f1 = __half22float2(*(__half2*)&m.y);
            acc.x = fmaf(v, f0.x, acc.x);
            acc.y = fmaf(v, f0.y, acc.y);
            acc.z = fmaf(v, f1.x, acc.z);
            acc.w = fmaf(v, f1.y, acc.w);
        }
    }

    acc.x = fmaxf(acc.x, 0.f); acc.y = fmaxf(acc.y, 0.f);
    acc.z = fmaxf(acc.z, 0.f); acc.w = fmaxf(acc.w, 0.f);

    float sm = acc.x + acc.y + acc.z + acc.w;
    #pragma unroll
    for (int o = 16; o; o >>= 1) sm += __shfl_xor_sync(0xffffffffu, sm, o);
    float mu = sm * (1.f / 128.f);

    float dx = acc.x - mu, dy = acc.y - mu, dz = acc.z - mu, dw = acc.w - mu;
    float q = dx * dx + dy * dy + dz * dz + dw * dw;
    #pragma unroll
    for (int o = 16; o; o >>= 1) q += __shfl_xor_sync(0xffffffffu, q, o);
    float rs = rsqrtf(q * (1.f / 128.f) + LN_EPS);

    float4 g = ((const float4*)gamma)[lane];
    float4 b = ((const float4*)beta)[lane];
    float4 o;
    o.x = dx * rs * g.x + b.x;
    o.y = dy * rs * g.y + b.y;
    o.z = dz * rs * g.z + b.z;
    o.w = dw * rs * g.w + b.w;
    ((float4*)(g_h2 + (size_t)row * D))[lane] = o;
}

// ---------------- masked batch gather: 4 rows/warp, streaming stores ----------------
__global__ void gather_kernel(const int* __restrict__ x, float* __restrict__ out) {
    int w = blockIdx.x * 8 + (threadIdx.x >> 5);
    int b0 = w * 4;
    if (b0 >= BATCH) return;
    int lane = threadIdx.x & 31;

    int xi[4];
    #pragma unroll
    for (int u = 0; u < 4; u++) xi[u] = x[b0 + u];

    float4 o[4];
    #pragma unroll
    for (int u = 0; u < 4; u++) {
        o[u] = make_float4(0.f, 0.f, 0.f, 0.f);
        if (xi[u] >= 1 && xi[u] <= N_NODES)
            o[u] = ((const float4*)(g_h2 + (size_t)(xi[u] - 1) * D))[lane];
    }
    #pragma unroll
    for (int u = 0; u < 4; u++)
        __stcs((float4*)(out + (size_t)(b0 + u) * D) + lane, o[u]);
}

extern "C" void kernel_launch(void* const* d_in, const int* in_sizes, int n_in,
                              void* d_out, int out_size) {
    const int*   x     = (const int*)d_in[0];
    const float* emb   = (const float*)d_in[1];
    const float* W     = (const float*)d_in[2];
    const float* bias  = (const float*)d_in[3];
    const float* vals  = (const float*)d_in[4];
    const int*   rows  = (const int*)d_in[5];
    const int*   cols  = (const int*)d_in[6];
    const float* gamma = (const float*)d_in[7];
    const float* beta  = (const float*)d_in[8];
    float* out = (float*)d_out;

    static cudaStream_t s2 = nullptr;
    static cudaEvent_t evFork = nullptr, evJoin = nullptr;
    if (s2 == nullptr) {
        cudaStreamCreateWithFlags(&s2, cudaStreamNonBlocking);
        cudaEventCreateWithFlags(&evFork, cudaEventDisableTiming);
        cudaEventCreateWithFlags(&evJoin, cudaEventDisableTiming);
    }

    cudaFuncSetAttribute(gemm_kernel, cudaFuncAttributeMaxDynamicSharedMemorySize, GEMM_SMEM);

    cudaEventRecord(evFork, 0);
    cudaStreamWaitEvent(s2, evFork, 0);

    zero_cnt_kernel<<<(N_NODES + 255) / 256, 256, 0, s2>>>();
    hist_kernel<<<(N_EDGES + 255) / 256, 256, 0, s2>>>(rows);
    scanA_kernel<<<NBLK, SCAN_CHUNK, 0, s2>>>();
    scanB_kernel<<<1, 128, 0, s2>>>();
    scanC_kernel<<<NBLK, SCAN_CHUNK, 0, s2>>>();
    scatter_kernel<<<(N_EDGES + 255) / 256, 256, 0, s2>>>(vals, rows, cols);

    wconv_kernel<<<(D * D + 255) / 256, 256>>>(W);
    gemm_kernel<<<(N_NODES + BLK_ROWS - 1) / BLK_ROWS, 256, GEMM_SMEM>>>(emb, bias);

    cudaEventRecord(evJoin, s2);
    cudaStreamWaitEvent(0, evJoin, 0);

    spmm_ln_kernel<<<(N_NODES + 7) / 8, 256>>>(gamma, beta);
    gather_kernel<<<(BATCH / 4 + 7) / 8, 256>>>(x, out);
}

// round 9
// speedup vs baseline: 1.9570x; 1.0356x over previous
#include <cuda_runtime.h>
#include <cuda_bf16.h>
#include <cuda_fp16.h>
#include <mma.h>

#define N_NODES 100000
#define D 128
#define N_EDGES 1600000
#define BATCH 500000
#define LN_EPS 1e-5f
#define SCAN_CHUNK 1024
#define NBLK ((N_NODES + SCAN_CHUNK - 1) / SCAN_CHUNK)   // 98

using namespace nvcuda;

// Scratch (device globals; no allocation allowed)
__device__ __align__(128) __half g_h1h[N_NODES * D]; // GEMM output (fp16)
__device__ __align__(128) __half g_h2h[N_NODES * D]; // LN output (fp16)
__device__ __align__(128) int2  g_epack[N_EDGES];    // CSR-permuted {col, val}
__device__ int g_eloc[N_EDGES];
__device__ int g_cnt[N_NODES];
__device__ int g_rowptr[N_NODES + 1];
__device__ int g_bsum[NBLK];
__device__ __align__(128) __nv_bfloat16 g_Wh[D * D];
__device__ __align__(128) __nv_bfloat16 g_Wl[D * D];

#define LDA 136
#define LDB 136
#define LDC 132
#define BLK_ROWS 64
#define GEMM_SMEM (128 * LDB * 2 * 2 + BLK_ROWS * LDA * 2 * 2)   // 104448

// ---------------- W pre-conversion (once) ----------------
__global__ void wconv_kernel(const float* __restrict__ W) {
    int i = blockIdx.x * blockDim.x + threadIdx.x;
    if (i < D * D) {
        float wv = W[i];
        __nv_bfloat16 whi = __float2bfloat16(wv);
        g_Wh[i] = whi;
        g_Wl[i] = __float2bfloat16(wv - __bfloat162float(whi));
    }
}

// ---------------- GEMM: h1 = emb @ W + bias (bf16 hi/lo, fp32 accum, fp16 store) ------
__global__ void gemm_kernel(const float* __restrict__ emb,
                            const float* __restrict__ bias) {
    extern __shared__ __nv_bfloat16 smem[];
    __nv_bfloat16* sWh = smem;
    __nv_bfloat16* sWl = sWh + 128 * LDB;
    __nv_bfloat16* sAh = sWl + 128 * LDB;
    __nv_bfloat16* sAl = sAh + BLK_ROWS * LDA;
    float* sC = (float*)sAh;

    int tid = threadIdx.x;
    int wid = tid >> 5;
    int wr = wid >> 1;
    int wc = wid & 1;
    int block_row = blockIdx.x * BLK_ROWS;

    for (int i = tid; i < 128 * 16; i += 256) {
        int r = i >> 4, q = i & 15;
        ((uint4*)(sWh + r * LDB))[q] = ((const uint4*)(g_Wh + r * D))[q];
        ((uint4*)(sWl + r * LDB))[q] = ((const uint4*)(g_Wl + r * D))[q];
    }
    for (int i = tid; i < BLK_ROWS * 32; i += 256) {
        int r = i >> 5, c4 = i & 31;
        int grow = block_row + r;
        float4 a = make_float4(0.f, 0.f, 0.f, 0.f);
        if (grow < N_NODES) a = ((const float4*)(emb + (size_t)grow * D))[c4];
        __nv_bfloat16 h0 = __float2bfloat16(a.x), h1 = __float2bfloat16(a.y);
        __nv_bfloat16 h2 = __float2bfloat16(a.z), h3 = __float2bfloat16(a.w);
        __nv_bfloat16 l0 = __float2bfloat16(a.x - __bfloat162float(h0));
        __nv_bfloat16 l1 = __float2bfloat16(a.y - __bfloat162float(h1));
        __nv_bfloat16 l2 = __float2bfloat16(a.z - __bfloat162float(h2));
        __nv_bfloat16 l3 = __float2bfloat16(a.w - __bfloat162float(h3));
        __nv_bfloat162* ph = (__nv_bfloat162*)(sAh + r * LDA);
        __nv_bfloat162* pl = (__nv_bfloat162*)(sAl + r * LDA);
        ph[c4 * 2]     = __nv_bfloat162(h0, h1);
        ph[c4 * 2 + 1] = __nv_bfloat162(h2, h3);
        pl[c4 * 2]     = __nv_bfloat162(l0, l1);
        pl[c4 * 2 + 1] = __nv_bfloat162(l2, l3);
    }
    __syncthreads();

    wmma::fragment<wmma::accumulator, 16, 16, 16, float> acc[4];
    #pragma unroll
    for (int c = 0; c < 4; c++) wmma::fill_fragment(acc[c], 0.f);

    #pragma unroll
    for (int k = 0; k < 8; k++) {
        wmma::fragment<wmma::matrix_a, 16, 16, 16, __nv_bfloat16, wmma::row_major> ah, al;
        wmma::load_matrix_sync(ah, sAh + wr * 16 * LDA + k * 16, LDA);
        wmma::load_matrix_sync(al, sAl + wr * 16 * LDA + k * 16, LDA);
        #pragma unroll
        for (int c = 0; c < 4; c++) {
            int cc = wc * 64 + c * 16;
            wmma::fragment<wmma::matrix_b, 16, 16, 16, __nv_bfloat16, wmma::row_major> bh, bl;
            wmma::load_matrix_sync(bh, sWh + k * 16 * LDB + cc, LDB);
            wmma::load_matrix_sync(bl, sWl + k * 16 * LDB + cc, LDB);
            wmma::mma_sync(acc[c], ah, bh, acc[c]);
            wmma::mma_sync(acc[c], ah, bl, acc[c]);
            wmma::mma_sync(acc[c], al, bh, acc[c]);
        }
    }
    __syncthreads();
    #pragma unroll
    for (int c = 0; c < 4; c++)
        wmma::store_matrix_sync(sC + wr * 16 * LDC + wc * 64 + c * 16, acc[c],
                                LDC, wmma::mem_row_major);
    __syncthreads();

    for (int i = tid; i < BLK_ROWS * 32; i += 256) {
        int r = i >> 5, c4 = i & 31;
        int grow = block_row + r;
        if (grow < N_NODES) {
            float4 cv = ((const float4*)(sC + r * LDC))[c4];
            float4 bv = ((const float4*)bias)[c4];
            __half2* p = (__half2*)(g_h1h + (size_t)grow * D);
            p[c4 * 2]     = __floats2half2_rn(cv.x + bv.x, cv.y + bv.y);
            p[c4 * 2 + 1] = __floats2half2_rn(cv.z + bv.z, cv.w + bv.w);
        }
    }
}

// ---------------- CSR build ----------------
__global__ void zero_cnt_kernel() {
    int i = blockIdx.x * blockDim.x + threadIdx.x;
    if (i < N_NODES) g_cnt[i] = 0;
}

__global__ void hist_kernel(const int* __restrict__ rows) {
    int e = blockIdx.x * blockDim.x + threadIdx.x;
    if (e < N_EDGES) g_eloc[e] = atomicAdd(&g_cnt[rows[e]], 1);
}

// shfl-based inclusive scan over 1024 elements per block
__global__ void scanA_kernel() {
    __shared__ int ws[32];
    int tid = threadIdx.x;
    int lane = tid & 31, w = tid >> 5;
    int idx = blockIdx.x * SCAN_CHUNK + tid;
    int v = (idx < N_NODES) ? g_cnt[idx] : 0;
    int inc = v;
    #pragma unroll
    for (int off = 1; off < 32; off <<= 1) {
        int t = __shfl_up_sync(0xffffffffu, inc, off);
        if (lane >= off) inc += t;
    }
    if (lane == 31) ws[w] = inc;
    __syncthreads();
    if (w == 0) {
        int b = ws[lane];
        #pragma unroll
        for (int off = 1; off < 32; off <<= 1) {
            int t = __shfl_up_sync(0xffffffffu, b, off);
            if (lane >= off) b += t;
        }
        ws[lane] = b;
    }
    __syncthreads();
    int total = inc + (w ? ws[w - 1] : 0);
    if (idx < N_NODES) g_rowptr[idx + 1] = total;
    if (tid == SCAN_CHUNK - 1) g_bsum[blockIdx.x] = total;
}

// exclusive scan over NBLK=98 block sums
__global__ void scanB_kernel() {
    int tid = threadIdx.x;          // 128 threads
    int lane = tid & 31, w = tid >> 5;
    int v = (tid < NBLK) ? g_bsum[tid] : 0;
    int inc = v;
    #pragma unroll
    for (int off = 1; off < 32; off <<= 1) {
        int t = __shfl_up_sync(0xffffffffu, inc, off);
        if (lane >= off) inc += t;
    }
    __shared__ int ws[4];
    if (lane == 31) ws[w] = inc;
    __syncthreads();
    int add = 0;
    #pragma unroll
    for (int i = 0; i < 4; i++) if (i < w) add += ws[i];
    if (tid < NBLK) g_bsum[tid] = inc + add - v;   // exclusive
}

__global__ void scanC_kernel() {
    int idx = blockIdx.x * SCAN_CHUNK + threadIdx.x;
    if (idx < N_NODES) g_rowptr[idx + 1] += g_bsum[blockIdx.x];
    if (idx == 0) g_rowptr[0] = 0;
}

__global__ void scatter_kernel(const float* __restrict__ vals,
                               const int* __restrict__ rows,
                               const int* __restrict__ cols) {
    int e = blockIdx.x * blockDim.x + threadIdx.x;
    if (e >= N_EDGES) return;
    int p = g_rowptr[rows[e]] + g_eloc[e];
    g_epack[p] = make_int2(cols[e], __float_as_int(vals[e]));
}

// ---------------- fused SpMM + ReLU + LayerNorm: warp/row, fp16 in+out ----------------
__global__ void spmm_ln_kernel(const float* __restrict__ gamma,
                               const float* __restrict__ beta) {
    int row = blockIdx.x * 8 + (threadIdx.x >> 5);
    if (row >= N_NODES) return;
    int lane = threadIdx.x & 31;
    int s = g_rowptr[row];
    int e = g_rowptr[row + 1];

    float4 acc = make_float4(0.f, 0.f, 0.f, 0.f);
    for (int base = s; base < e; base += 32) {
        int n = min(32, e - base);
        int2 ev = make_int2(0, 0);
        if (base + lane < e) ev = g_epack[base + lane];
        int j = 0;
        for (; j + 8 <= n; j += 8) {
            float v[8]; uint2 m[8];
            #pragma unroll
            for (int u = 0; u < 8; u++) {
                int c = __shfl_sync(0xffffffffu, ev.x, j + u);
                v[u] = __int_as_float(__shfl_sync(0xffffffffu, ev.y, j + u));
                m[u] = ((const uint2*)(g_h1h + (size_t)c * D))[lane];
            }
            #pragma unroll
            for (int u = 0; u < 8; u++) {
                float2 f0 = __half22float2(*(__half2*)&m[u].x);
                float2 f1 = __half22float2(*(__half2*)&m[u].y);
                acc.x = fmaf(v[u], f0.x, acc.x);
                acc.y = fmaf(v[u], f0.y, acc.y);
                acc.z = fmaf(v[u], f1.x, acc.z);
                acc.w = fmaf(v[u], f1.y, acc.w);
            }
        }
        for (; j < n; j++) {
            int   c = __shfl_sync(0xffffffffu, ev.x, j);
            float v = __int_as_float(__shfl_sync(0xffffffffu, ev.y, j));
            uint2 m = ((const uint2*)(g_h1h + (size_t)c * D))[lane];
            float2 f0 = __half22float2(*(__half2*)&m.x);
            float2 f1 = __half22float2(*(__half2*)&m.y);
            acc.x = fmaf(v, f0.x, acc.x);
            acc.y = fmaf(v, f0.y, acc.y);
            acc.z = fmaf(v, f1.x, acc.z);
            acc.w = fmaf(v, f1.y, acc.w);
        }
    }

    acc.x = fmaxf(acc.x, 0.f); acc.y = fmaxf(acc.y, 0.f);
    acc.z = fmaxf(acc.z, 0.f); acc.w = fmaxf(acc.w, 0.f);

    float sm = acc.x + acc.y + acc.z + acc.w;
    #pragma unroll
    for (int o = 16; o; o >>= 1) sm += __shfl_xor_sync(0xffffffffu, sm, o);
    float mu = sm * (1.f / 128.f);

    float dx = acc.x - mu, dy = acc.y - mu, dz = acc.z - mu, dw = acc.w - mu;
    float q = dx * dx + dy * dy + dz * dz + dw * dw;
    #pragma unroll
    for (int o = 16; o; o >>= 1) q += __shfl_xor_sync(0xffffffffu, q, o);
    float rs = rsqrtf(q * (1.f / 128.f) + LN_EPS);

    float4 g = ((const float4*)gamma)[lane];
    float4 b = ((const float4*)beta)[lane];
    __half2* p = (__half2*)(g_h2h + (size_t)row * D);
    p[lane * 2]     = __floats2half2_rn(dx * rs * g.x + b.x, dy * rs * g.y + b.y);
    p[lane * 2 + 1] = __floats2half2_rn(dz * rs * g.z + b.z, dw * rs * g.w + b.w);
}

// ---------------- masked batch gather: 4 rows/warp, fp16 read, fp32 stream-out --------
__global__ void gather_kernel(const int* __restrict__ x, float* __restrict__ out) {
    int w = blockIdx.x * 8 + (threadIdx.x >> 5);
    int b0 = w * 4;
    if (b0 >= BATCH) return;
    int lane = threadIdx.x & 31;

    int xi[4];
    #pragma unroll
    for (int u = 0; u < 4; u++) xi[u] = x[b0 + u];

    uint2 m[4];
    #pragma unroll
    for (int u = 0; u < 4; u++) {
        m[u] = make_uint2(0u, 0u);
        if (xi[u] >= 1 && xi[u] <= N_NODES)
            m[u] = ((const uint2*)(g_h2h + (size_t)(xi[u] - 1) * D))[lane];
    }
    #pragma unroll
    for (int u = 0; u < 4; u++) {
        float2 f0 = __half22float2(*(__half2*)&m[u].x);
        float2 f1 = __half22float2(*(__half2*)&m[u].y);
        __stcs((float4*)(out + (size_t)(b0 + u) * D) + lane,
               make_float4(f0.x, f0.y, f1.x, f1.y));
    }
}

extern "C" void kernel_launch(void* const* d_in, const int* in_sizes, int n_in,
                              void* d_out, int out_size) {
    const int*   x     = (const int*)d_in[0];
    const float* emb   = (const float*)d_in[1];
    const float* W     = (const float*)d_in[2];
    const float* bias  = (const float*)d_in[3];
    const float* vals  = (const float*)d_in[4];
    const int*   rows  = (const int*)d_in[5];
    const int*   cols  = (const int*)d_in[6];
    const float* gamma = (const float*)d_in[7];
    const float* beta  = (const float*)d_in[8];
    float* out = (float*)d_out;

    static cudaStream_t s2 = nullptr;
    static cudaEvent_t evFork = nullptr, evJoin = nullptr;
    if (s2 == nullptr) {
        cudaStreamCreateWithFlags(&s2, cudaStreamNonBlocking);
        cudaEventCreateWithFlags(&evFork, cudaEventDisableTiming);
        cudaEventCreateWithFlags(&evJoin, cudaEventDisableTiming);
    }

    cudaFuncSetAttribute(gemm_kernel, cudaFuncAttributeMaxDynamicSharedMemorySize, GEMM_SMEM);

    cudaEventRecord(evFork, 0);
    cudaStreamWaitEvent(s2, evFork, 0);

    zero_cnt_kernel<<<(N_NODES + 255) / 256, 256, 0, s2>>>();
    hist_kernel<<<(N_EDGES + 255) / 256, 256, 0, s2>>>(rows);
    scanA_kernel<<<NBLK, SCAN_CHUNK, 0, s2>>>();
    scanB_kernel<<<1, 128, 0, s2>>>();
    scanC_kernel<<<NBLK, SCAN_CHUNK, 0, s2>>>();
    scatter_kernel<<<(N_EDGES + 255) / 256, 256, 0, s2>>>(vals, rows, cols);

    wconv_kernel<<<(D * D + 255) / 256, 256>>>(W);
    gemm_kernel<<<(N_NODES + BLK_ROWS - 1) / BLK_ROWS, 256, GEMM_SMEM>>>(emb, bias);

    cudaEventRecord(evJoin, s2);
    cudaStreamWaitEvent(0, evJoin, 0);

    spmm_ln_kernel<<<(N_NODES + 7) / 8, 256>>>(gamma, beta);
    gather_kernel<<<(BATCH / 4 + 7) / 8, 256>>>(x, out);
}

// round 10
// speedup vs baseline: 2.1175x; 1.0820x over previous
#include <cuda_runtime.h>
#include <cuda_bf16.h>
#include <cuda_fp16.h>
#include <mma.h>

#define N_NODES 100000
#define D 128
#define N_EDGES 1600000
#define BATCH 500000
#define LN_EPS 1e-5f
#define SCAN_CHUNK 1024
#define NBLK ((N_NODES + SCAN_CHUNK - 1) / SCAN_CHUNK)   // 98

using namespace nvcuda;

// Scratch (device globals; no allocation allowed)
__device__ __align__(128) __half g_h1h[N_NODES * D]; // GEMM output (fp16)
__device__ __align__(128) int2  g_epack[N_EDGES];    // CSR-permuted {col, val}
__device__ int g_eloc[N_EDGES];
__device__ int g_elocb[BATCH];
__device__ int g_bidx[BATCH];                        // batch ids grouped by node
__device__ int g_cnt[N_NODES];
__device__ int g_cntb[N_NODES];
__device__ int g_rowptr[N_NODES + 1];
__device__ int g_rowptrb[N_NODES + 1];
__device__ int g_bsumA[NBLK];
__device__ int g_bsumB[NBLK];
__device__ __align__(128) __nv_bfloat16 g_Wh[D * D];
__device__ __align__(128) __nv_bfloat16 g_Wl[D * D];

#define LDA 136
#define LDB 136
#define LDC 132
#define BLK_ROWS 64
#define GEMM_SMEM (128 * LDB * 2 * 2 + BLK_ROWS * LDA * 2 * 2)   // 104448

// ---------------- W pre-conversion (once) ----------------
__global__ void wconv_kernel(const float* __restrict__ W) {
    int i = blockIdx.x * blockDim.x + threadIdx.x;
    if (i < D * D) {
        float wv = W[i];
        __nv_bfloat16 whi = __float2bfloat16(wv);
        g_Wh[i] = whi;
        g_Wl[i] = __float2bfloat16(wv - __bfloat162float(whi));
    }
}

// ---------------- GEMM: h1 = emb @ W + bias (bf16 hi/lo, fp32 accum, fp16 store) ------
__global__ void gemm_kernel(const float* __restrict__ emb,
                            const float* __restrict__ bias) {
    extern __shared__ __nv_bfloat16 smem[];
    __nv_bfloat16* sWh = smem;
    __nv_bfloat16* sWl = sWh + 128 * LDB;
    __nv_bfloat16* sAh = sWl + 128 * LDB;
    __nv_bfloat16* sAl = sAh + BLK_ROWS * LDA;
    float* sC = (float*)sAh;

    int tid = threadIdx.x;
    int wid = tid >> 5;
    int wr = wid >> 1;
    int wc = wid & 1;
    int block_row = blockIdx.x * BLK_ROWS;

    for (int i = tid; i < 128 * 16; i += 256) {
        int r = i >> 4, q = i & 15;
        ((uint4*)(sWh + r * LDB))[q] = ((const uint4*)(g_Wh + r * D))[q];
        ((uint4*)(sWl + r * LDB))[q] = ((const uint4*)(g_Wl + r * D))[q];
    }
    for (int i = tid; i < BLK_ROWS * 32; i += 256) {
        int r = i >> 5, c4 = i & 31;
        int grow = block_row + r;
        float4 a = make_float4(0.f, 0.f, 0.f, 0.f);
        if (grow < N_NODES) a = ((const float4*)(emb + (size_t)grow * D))[c4];
        __nv_bfloat16 h0 = __float2bfloat16(a.x), h1 = __float2bfloat16(a.y);
        __nv_bfloat16 h2 = __float2bfloat16(a.z), h3 = __float2bfloat16(a.w);
        __nv_bfloat16 l0 = __float2bfloat16(a.x - __bfloat162float(h0));
        __nv_bfloat16 l1 = __float2bfloat16(a.y - __bfloat162float(h1));
        __nv_bfloat16 l2 = __float2bfloat16(a.z - __bfloat162float(h2));
        __nv_bfloat16 l3 = __float2bfloat16(a.w - __bfloat162float(h3));
        __nv_bfloat162* ph = (__nv_bfloat162*)(sAh + r * LDA);
        __nv_bfloat162* pl = (__nv_bfloat162*)(sAl + r * LDA);
        ph[c4 * 2]     = __nv_bfloat162(h0, h1);
        ph[c4 * 2 + 1] = __nv_bfloat162(h2, h3);
        pl[c4 * 2]     = __nv_bfloat162(l0, l1);
        pl[c4 * 2 + 1] = __nv_bfloat162(l2, l3);
    }
    __syncthreads();

    wmma::fragment<wmma::accumulator, 16, 16, 16, float> acc[4];
    #pragma unroll
    for (int c = 0; c < 4; c++) wmma::fill_fragment(acc[c], 0.f);

    #pragma unroll
    for (int k = 0; k < 8; k++) {
        wmma::fragment<wmma::matrix_a, 16, 16, 16, __nv_bfloat16, wmma::row_major> ah, al;
        wmma::load_matrix_sync(ah, sAh + wr * 16 * LDA + k * 16, LDA);
        wmma::load_matrix_sync(al, sAl + wr * 16 * LDA + k * 16, LDA);
        #pragma unroll
        for (int c = 0; c < 4; c++) {
            int cc = wc * 64 + c * 16;
            wmma::fragment<wmma::matrix_b, 16, 16, 16, __nv_bfloat16, wmma::row_major> bh, bl;
            wmma::load_matrix_sync(bh, sWh + k * 16 * LDB + cc, LDB);
            wmma::load_matrix_sync(bl, sWl + k * 16 * LDB + cc, LDB);
            wmma::mma_sync(acc[c], ah, bh, acc[c]);
            wmma::mma_sync(acc[c], ah, bl, acc[c]);
            wmma::mma_sync(acc[c], al, bh, acc[c]);
        }
    }
    __syncthreads();
    #pragma unroll
    for (int c = 0; c < 4; c++)
        wmma::store_matrix_sync(sC + wr * 16 * LDC + wc * 64 + c * 16, acc[c],
                                LDC, wmma::mem_row_major);
    __syncthreads();

    for (int i = tid; i < BLK_ROWS * 32; i += 256) {
        int r = i >> 5, c4 = i & 31;
        int grow = block_row + r;
        if (grow < N_NODES) {
            float4 cv = ((const float4*)(sC + r * LDC))[c4];
            float4 bv = ((const float4*)bias)[c4];
            __half2* p = (__half2*)(g_h1h + (size_t)grow * D);
            p[c4 * 2]     = __floats2half2_rn(cv.x + bv.x, cv.y + bv.y);
            p[c4 * 2 + 1] = __floats2half2_rn(cv.z + bv.z, cv.w + bv.w);
        }
    }
}

// ---------------- dual CSR build (edges by row; batch ids by node) ----------------
__global__ void zero_cnt_kernel() {
    int i = blockIdx.x * blockDim.x + threadIdx.x;
    if (i < N_NODES) { g_cnt[i] = 0; g_cntb[i] = 0; }
}

// fused histogram pass: edges then batch
__global__ void hist_kernel(const int* __restrict__ rows, const int* __restrict__ x) {
    int i = blockIdx.x * blockDim.x + threadIdx.x;
    if (i < N_EDGES) g_eloc[i] = atomicAdd(&g_cnt[rows[i]], 1);
    int b = i - N_EDGES;
    if (b >= 0 && b < BATCH) {
        int xv = x[b];
        if (xv >= 1 && xv <= N_NODES) g_elocb[b] = atomicAdd(&g_cntb[xv - 1], 1);
        else g_elocb[b] = -1;
    }
}

// shfl scan over 1024/block; blockIdx.y selects {edges, batch} array
__global__ void scanA_kernel() {
    __shared__ int ws[32];
    int a = blockIdx.y;
    const int* cnt = a ? g_cntb : g_cnt;
    int* rp = a ? g_rowptrb : g_rowptr;
    int* bs = a ? g_bsumB : g_bsumA;
    int tid = threadIdx.x;
    int lane = tid & 31, w = tid >> 5;
    int idx = blockIdx.x * SCAN_CHUNK + tid;
    int v = (idx < N_NODES) ? cnt[idx] : 0;
    int inc = v;
    #pragma unroll
    for (int off = 1; off < 32; off <<= 1) {
        int t = __shfl_up_sync(0xffffffffu, inc, off);
        if (lane >= off) inc += t;
    }
    if (lane == 31) ws[w] = inc;
    __syncthreads();
    if (w == 0) {
        int b = ws[lane];
        #pragma unroll
        for (int off = 1; off < 32; off <<= 1) {
            int t = __shfl_up_sync(0xffffffffu, b, off);
            if (lane >= off) b += t;
        }
        ws[lane] = b;
    }
    __syncthreads();
    int total = inc + (w ? ws[w - 1] : 0);
    if (idx < N_NODES) rp[idx + 1] = total;
    if (tid == SCAN_CHUNK - 1) bs[blockIdx.x] = total;
}

// exclusive scan over both NBLK block-sum arrays (256 thr = 2 x 128)
__global__ void scanB_kernel() {
    int tid = threadIdx.x;
    int a = tid >> 7;
    int t = tid & 127;
    int lane = t & 31, w = t >> 5;
    int* bs = a ? g_bsumB : g_bsumA;
    int v = (t < NBLK) ? bs[t] : 0;
    int inc = v;
    #pragma unroll
    for (int off = 1; off < 32; off <<= 1) {
        int tt = __shfl_up_sync(0xffffffffu, inc, off);
        if (lane >= off) inc += tt;
    }
    __shared__ int ws[2][4];
    if (lane == 31) ws[a][w] = inc;
    __syncthreads();
    int add = 0;
    #pragma unroll
    for (int i = 0; i < 4; i++) if (i < w) add += ws[a][i];
    if (t < NBLK) bs[t] = inc + add - v;   // exclusive
}

__global__ void scanC_kernel() {
    int a = blockIdx.y;
    int* rp = a ? g_rowptrb : g_rowptr;
    const int* bs = a ? g_bsumB : g_bsumA;
    int idx = blockIdx.x * SCAN_CHUNK + threadIdx.x;
    if (idx < N_NODES) rp[idx + 1] += bs[blockIdx.x];
    if (idx == 0) rp[0] = 0;
}

// fused scatter: edge records + batch ids (+ zero rows for invalid x)
__global__ void scatter_kernel(const float* __restrict__ vals,
                               const int* __restrict__ rows,
                               const int* __restrict__ cols,
                               const int* __restrict__ x,
                               float* __restrict__ out) {
    int i = blockIdx.x * blockDim.x + threadIdx.x;
    if (i < N_EDGES) {
        int p = g_rowptr[rows[i]] + g_eloc[i];
        g_epack[p] = make_int2(cols[i], __float_as_int(vals[i]));
    }
    int b = i - N_EDGES;
    if (b >= 0 && b < BATCH) {
        int xv = x[b];
        if (xv >= 1 && xv <= N_NODES) {
            g_bidx[g_rowptrb[xv - 1] + g_elocb[b]] = b;
        } else {
            float4* o = (float4*)(out + (size_t)b * D);
            #pragma unroll
            for (int k = 0; k < 32; k++) o[k] = make_float4(0.f, 0.f, 0.f, 0.f);
        }
    }
}

// ---------------- fused SpMM + ReLU + LayerNorm + direct batch scatter ----------------
__global__ void spmm_ln_kernel(const float* __restrict__ gamma,
                               const float* __restrict__ beta,
                               float* __restrict__ out) {
    int row = blockIdx.x * 8 + (threadIdx.x >> 5);
    if (row >= N_NODES) return;
    int lane = threadIdx.x & 31;
    int s = g_rowptr[row];
    int e = g_rowptr[row + 1];

    float4 acc = make_float4(0.f, 0.f, 0.f, 0.f);
    for (int base = s; base < e; base += 32) {
        int n = min(32, e - base);
        int2 ev = make_int2(0, 0);
        if (base + lane < e) ev = g_epack[base + lane];
        int j = 0;
        for (; j + 8 <= n; j += 8) {
            float v[8]; uint2 m[8];
            #pragma unroll
            for (int u = 0; u < 8; u++) {
                int c = __shfl_sync(0xffffffffu, ev.x, j + u);
                v[u] = __int_as_float(__shfl_sync(0xffffffffu, ev.y, j + u));
                m[u] = ((const uint2*)(g_h1h + (size_t)c * D))[lane];
            }
            #pragma unroll
            for (int u = 0; u < 8; u++) {
                float2 f0 = __half22float2(*(__half2*)&m[u].x);
                float2 f1 = __half22float2(*(__half2*)&m[u].y);
                acc.x = fmaf(v[u], f0.x, acc.x);
                acc.y = fmaf(v[u], f0.y, acc.y);
                acc.z = fmaf(v[u], f1.x, acc.z);
                acc.w = fmaf(v[u], f1.y, acc.w);
            }
        }
        for (; j < n; j++) {
            int   c = __shfl_sync(0xffffffffu, ev.x, j);
            float v = __int_as_float(__shfl_sync(0xffffffffu, ev.y, j));
            uint2 m = ((const uint2*)(g_h1h + (size_t)c * D))[lane];
            float2 f0 = __half22float2(*(__half2*)&m.x);
            float2 f1 = __half22float2(*(__half2*)&m.y);
            acc.x = fmaf(v, f0.x, acc.x);
            acc.y = fmaf(v, f0.y, acc.y);
            acc.z = fmaf(v, f1.x, acc.z);
            acc.w = fmaf(v, f1.y, acc.w);
        }
    }

    acc.x = fmaxf(acc.x, 0.f); acc.y = fmaxf(acc.y, 0.f);
    acc.z = fmaxf(acc.z, 0.f); acc.w = fmaxf(acc.w, 0.f);

    float sm = acc.x + acc.y + acc.z + acc.w;
    #pragma unroll
    for (int o = 16; o; o >>= 1) sm += __shfl_xor_sync(0xffffffffu, sm, o);
    float mu = sm * (1.f / 128.f);

    float dx = acc.x - mu, dy = acc.y - mu, dz = acc.z - mu, dw = acc.w - mu;
    float q = dx * dx + dy * dy + dz * dz + dw * dw;
    #pragma unroll
    for (int o = 16; o; o >>= 1) q += __shfl_xor_sync(0xffffffffu, q, o);
    float rs = rsqrtf(q * (1.f / 128.f) + LN_EPS);

    float4 g = ((const float4*)gamma)[lane];
    float4 b = ((const float4*)beta)[lane];
    float4 o;
    o.x = dx * rs * g.x + b.x;
    o.y = dy * rs * g.y + b.y;
    o.z = dz * rs * g.z + b.z;
    o.w = dw * rs * g.w + b.w;

    // direct scatter to all batch positions referencing this node
    int sb = g_rowptrb[row];
    int eb = g_rowptrb[row + 1];
    for (int t = sb; t < eb; t++) {
        int b2 = g_bidx[t];
        __stcs((float4*)(out + (size_t)b2 * D) + lane, o);
    }
}

extern "C" void kernel_launch(void* const* d_in, const int* in_sizes, int n_in,
                              void* d_out, int out_size) {
    const int*   x     = (const int*)d_in[0];
    const float* emb   = (const float*)d_in[1];
    const float* W     = (const float*)d_in[2];
    const float* bias  = (const float*)d_in[3];
    const float* vals  = (const float*)d_in[4];
    const int*   rows  = (const int*)d_in[5];
    const int*   cols  = (const int*)d_in[6];
    const float* gamma = (const float*)d_in[7];
    const float* beta  = (const float*)d_in[8];
    float* out = (float*)d_out;

    static cudaStream_t s2 = nullptr;
    static cudaEvent_t evFork = nullptr, evJoin = nullptr;
    if (s2 == nullptr) {
        cudaStreamCreateWithFlags(&s2, cudaStreamNonBlocking);
        cudaEventCreateWithFlags(&evFork, cudaEventDisableTiming);
        cudaEventCreateWithFlags(&evJoin, cudaEventDisableTiming);
    }

    cudaFuncSetAttribute(gemm_kernel, cudaFuncAttributeMaxDynamicSharedMemorySize, GEMM_SMEM);

    cudaEventRecord(evFork, 0);
    cudaStreamWaitEvent(s2, evFork, 0);

    zero_cnt_kernel<<<(N_NODES + 255) / 256, 256, 0, s2>>>();
    hist_kernel<<<(N_EDGES + BATCH + 255) / 256, 256, 0, s2>>>(rows, x);
    scanA_kernel<<<dim3(NBLK, 2), SCAN_CHUNK, 0, s2>>>();
    scanB_kernel<<<1, 256, 0, s2>>>();
    scanC_kernel<<<dim3(NBLK, 2), SCAN_CHUNK, 0, s2>>>();
    scatter_kernel<<<(N_EDGES + BATCH + 255) / 256, 256, 0, s2>>>(vals, rows, cols, x, out);

    wconv_kernel<<<(D * D + 255) / 256, 256>>>(W);
    gemm_kernel<<<(N_NODES + BLK_ROWS - 1) / BLK_ROWS, 256, GEMM_SMEM>>>(emb, bias);

    cudaEventRecord(evJoin, s2);
    cudaStreamWaitEvent(0, evJoin, 0);

    spmm_ln_kernel<<<(N_NODES + 7) / 8, 256>>>(gamma, beta, out);
}